// round 14
// baseline (speedup 1.0000x reference)
#include <cuda_runtime.h>
#include <cuda_fp16.h>
#include <math.h>
#include <stdint.h>

// ---------------------------------------------------------------------------
// Problem constants
// ---------------------------------------------------------------------------
#define BB 4
#define TT 16
#define AA 512
#define ZZ 512
#define NFF 6
#define NROWS (BB*TT*AA)      // 32768
#define NCUR  (BB*AA)         // 2048
#define NBT   (BB*TT)         // 64

// ---------------------------------------------------------------------------
// Scratch (static device globals; no allocations allowed)
// ---------------------------------------------------------------------------
// fp32 scratch
__device__ float d_kv[NCUR*2*ZZ];        // [kc | vc] combined (stride 1024)
__device__ float d_e[NBT*ZZ];
// fp16 scratch
__device__ __half h_qln[NROWS*ZZ];       // LN(z_pred) (Q GEMM input)
__device__ __half h_q[NROWS*ZZ];         // q projection, pre-scaled (attn input)
__device__ __half h_att[NROWS*ZZ];       // attention out (Wo input)
__device__ __half h_cat[NROWS*2*ZZ];     // [o | z_pred] concat (gate GEMM input)
__device__ __half h_hg[NROWS*ZZ];        // gate hidden (gelu'd, half)
__device__ __half h_zc[NCUR*ZZ];         // z_current half
__device__ __half h_zmid[NROWS*ZZ];      // z_mid half (FF1 input + FF2 residual)
__device__ __half h_hid[NROWS*4*ZZ];     // FF hidden half (FF2 input)
__device__ __half h_w[3670016];          // transposed half weights [M,K]

// offsets into h_w
#define OFF_WQ   0
#define OFF_WK   262144
#define OFF_WV   524288           // contiguous after WK -> combined [1024,512]
#define OFF_WO   786432
#define OFF_WG1  1048576          // [512, 1024]
#define OFF_FF1  1572864          // [2048, 512]
#define OFF_FF2  2621440          // [512, 2048]

// ---------------------------------------------------------------------------
// Helpers
// ---------------------------------------------------------------------------
__device__ __forceinline__ float gelu_exact(float x) {
    return 0.5f * x * (1.0f + erff(x * 0.70710678118654752f));
}
__device__ __forceinline__ uint32_t smem_u32(const void* p) {
    uint32_t a;
    asm("{ .reg .u64 t; cvta.to.shared.u64 t, %1; cvt.u32.u64 %0, t; }"
        : "=r"(a) : "l"(p));
    return a;
}
__device__ __forceinline__ void cp_async16(uint32_t s, const void* g) {
    asm volatile("cp.async.cg.shared.global [%0], [%1], 16;" :: "r"(s), "l"(g));
}
__device__ __forceinline__ void cp_commit() {
    asm volatile("cp.async.commit_group;");
}
__device__ __forceinline__ void cp_wait0() { asm volatile("cp.async.wait_group 0;"); }
__device__ __forceinline__ void cp_wait1() { asm volatile("cp.async.wait_group 1;"); }

// m16n8k16 fp16 MMA, fp32 accumulate
__device__ __forceinline__ void mma16(float c[4], uint32_t a0, uint32_t a1,
                                      uint32_t a2, uint32_t a3,
                                      uint32_t b0, uint32_t b1) {
    asm volatile(
        "mma.sync.aligned.m16n8k16.row.col.f32.f16.f16.f32 "
        "{%0,%1,%2,%3},{%4,%5,%6,%7},{%8,%9},{%0,%1,%2,%3};"
        : "+f"(c[0]), "+f"(c[1]), "+f"(c[2]), "+f"(c[3])
        : "r"(a0), "r"(a1), "r"(a2), "r"(a3), "r"(b0), "r"(b1));
}

__device__ __forceinline__ void ldsm4(uint32_t& r0, uint32_t& r1,
                                      uint32_t& r2, uint32_t& r3, uint32_t a) {
    asm volatile("ldmatrix.sync.aligned.m8n8.x4.shared.b16 {%0,%1,%2,%3}, [%4];"
        : "=r"(r0), "=r"(r1), "=r"(r2), "=r"(r3) : "r"(a));
}

__device__ __forceinline__ float blockSum128(float v, float* sb) {
    #pragma unroll
    for (int o = 16; o > 0; o >>= 1) v += __shfl_down_sync(0xffffffffu, v, o);
    int w = threadIdx.x >> 5;
    if ((threadIdx.x & 31) == 0) sb[w] = v;
    __syncthreads();
    if (threadIdx.x < 32) {
        float r = (threadIdx.x < 4) ? sb[threadIdx.x] : 0.0f;
        #pragma unroll
        for (int o = 2; o > 0; o >>= 1) r += __shfl_down_sync(0xffffffffu, r, o);
        if (threadIdx.x == 0) sb[0] = r;
    }
    __syncthreads();
    float out = sb[0];
    __syncthreads();
    return out;
}

// ---------------------------------------------------------------------------
// Fused prep: ALL weight transposes + z_current halfcopy in ONE launch.
// ---------------------------------------------------------------------------
__device__ __forceinline__ void tr_tile(const float* __restrict__ x,
                                        __half* __restrict__ y,
                                        int K, int M, int tile, float scale) {
    __shared__ float t[32][33];
    int tilesX = M >> 5;
    int m0 = (tile % tilesX) * 32;
    int k0 = (tile / tilesX) * 32;
    int tx = threadIdx.x & 31, ty = threadIdx.x >> 5;
    #pragma unroll
    for (int i = 0; i < 32; i += 8)
        t[ty + i][tx] = x[(size_t)(k0 + ty + i) * M + m0 + tx];
    __syncthreads();
    #pragma unroll
    for (int i = 0; i < 32; i += 8)
        y[(size_t)(m0 + ty + i) * K + k0 + tx] = __float2half(t[tx][ty + i] * scale);
}

__global__ void prep_kernel(const float* __restrict__ Wq,
                            const float* __restrict__ Wk,
                            const float* __restrict__ Wv,
                            const float* __restrict__ Wo,
                            const float* __restrict__ Wg1,
                            const float* __restrict__ Wff1,
                            const float* __restrict__ Wff2,
                            const float* __restrict__ zcur,
                            __half* __restrict__ wh,
                            __half* __restrict__ zc) {
    int b = blockIdx.x;
    if (b < 256)        tr_tile(Wq,   wh + OFF_WQ,  512,  512,  b,        0.125f);
    else if (b < 512)   tr_tile(Wk,   wh + OFF_WK,  512,  512,  b - 256,  1.0f);
    else if (b < 768)   tr_tile(Wv,   wh + OFF_WV,  512,  512,  b - 512,  1.0f);
    else if (b < 1024)  tr_tile(Wo,   wh + OFF_WO,  512,  512,  b - 768,  1.0f);
    else if (b < 1536)  tr_tile(Wg1,  wh + OFF_WG1, 1024, 512,  b - 1024, 1.0f);
    else if (b < 2560)  tr_tile(Wff1, wh + OFF_FF1, 512,  2048, b - 1536, 1.0f);
    else if (b < 3584)  tr_tile(Wff2, wh + OFF_FF2, 2048, 512,  b - 2560, 1.0f);
    else {
        int i = (b - 3584) * 256 + threadIdx.x;   // i < 262144 = (NCUR*ZZ)/4
        float4 v = ((const float4*)zcur)[i];
        __half2* yo = (__half2*)zc;
        yo[2 * i + 0] = __floats2half2_rn(v.x, v.y);
        yo[2 * i + 1] = __floats2half2_rn(v.z, v.w);
    }
}

// ---------------------------------------------------------------------------
// LayerNorm (per 512-wide row), 128 threads/row; writes half LN output AND
// deposits half(z_pred) into the concat buffer's upper 512 columns.
// ---------------------------------------------------------------------------
__global__ void ln_kernel(const float* __restrict__ x,
                          const float* __restrict__ g,
                          const float* __restrict__ b,
                          __half* __restrict__ y,
                          __half* __restrict__ cat) {
    __shared__ float sb[32];
    int row = blockIdx.x;
    int tid = threadIdx.x;
    const float* xr = x + (size_t)row * ZZ;
    float v[4];
    float s = 0.f;
    #pragma unroll
    for (int k = 0; k < 4; k++) { v[k] = xr[tid + k * 128]; s += v[k]; }
    float mean = blockSum128(s, sb) * (1.0f / ZZ);
    float s2 = 0.f;
    #pragma unroll
    for (int k = 0; k < 4; k++) { float d = v[k] - mean; s2 += d * d; }
    float var = blockSum128(s2, sb) * (1.0f / ZZ);
    float rstd = rsqrtf(var + 1e-5f);
    __half* yr = y + (size_t)row * ZZ;
    __half* cr = cat + (size_t)row * (2 * ZZ) + ZZ;
    #pragma unroll
    for (int k = 0; k < 4; k++) {
        int c = tid + k * 128;
        yr[c] = __float2half((v[k] - mean) * rstd * g[c] + b[c]);
        cr[c] = __float2half(v[k]);
    }
}

// ---------------------------------------------------------------------------
// Edge embedding: fourier(actions) @ W_edge + b_edge -> @ We   (64 rows)
// ---------------------------------------------------------------------------
__global__ void edge_kernel(const float* __restrict__ actions,
                            const float* __restrict__ W_edge,
                            const float* __restrict__ b_edge,
                            const float* __restrict__ We,
                            float* __restrict__ eout) {
    __shared__ float feats[38];
    __shared__ float hid[64];
    int bt = blockIdx.x;
    int tid = threadIdx.x;
    if (tid == 0) {
        float dx = actions[bt * 4 + 0];
        float dy = actions[bt * 4 + 1];
        float th = actions[bt * 4 + 2];
        feats[0] = sinf(th);
        feats[1] = cosf(th);
        #pragma unroll
        for (int k = 0; k < NFF; k++) {
            float f = 3.14159265358979323846f * (float)(1 << k);
            feats[2 + 6 * k + 0] = sinf(f * dx);
            feats[2 + 6 * k + 1] = cosf(f * dx);
            feats[2 + 6 * k + 2] = sinf(f * dy);
            feats[2 + 6 * k + 3] = cosf(f * dy);
            feats[2 + 6 * k + 4] = sinf(f * th);
            feats[2 + 6 * k + 5] = cosf(f * th);
        }
    }
    __syncthreads();
    float h = b_edge[tid];
    #pragma unroll
    for (int j = 0; j < 38; j++) h += feats[j] * W_edge[j * 64 + tid];
    hid[tid] = h;
    __syncthreads();
    #pragma unroll
    for (int c = 0; c < 8; c++) {
        int col = c * 64 + tid;
        float acc = 0.f;
        #pragma unroll
        for (int j = 0; j < 64; j++) acc += hid[j] * We[j * ZZ + col];
        eout[(size_t)bt * ZZ + col] = acc;
    }
}

// ---------------------------------------------------------------------------
// fp16 tensor-core GEMM: C[N,M] = A[N,K] @ Bt[M,K]^T  (A, Bt half; fp32 accum)
// 128x128x64 tiles, 3-stage cp.async pipeline with ONE barrier per chunk
// (3 stages make the WAR barrier redundant; loads issue before the MMA block).
// 8 warps of 64x32, mma m16n8k16, ldmatrix.
// Epilogue: BIAS, GELU, RES (half, ldres), WF32 (C f32, stride M), WF16 (Ch, ldch)
// smem halves: As[3][128][72] + Bs[3][128][72] = 55296 halves = 110592 B
// ---------------------------------------------------------------------------
#define MM_SMEM (55296 * 2)

template<bool BIAS, bool GELU, bool RES, bool WF32, bool WF16>
__global__ void __launch_bounds__(256, 2)
mm_h(const __half* __restrict__ A, const __half* __restrict__ Bt,
     const float* __restrict__ bias, const __half* __restrict__ res,
     float* __restrict__ C, __half* __restrict__ Ch,
     int K, int M, int lda, int ldb, int ldch, int ldres) {
    extern __shared__ __half smh[];
    const uint32_t base = smem_u32(smh);

    const int tid = threadIdx.x;
    const int lane = tid & 31;
    const int wid = tid >> 5;
    const int wm = (wid >> 2) * 64;
    const int wn = (wid & 3) * 32;
    const int bRow = blockIdx.y * 128;
    const int bCol = blockIdx.x * 128;
    const int gid = lane >> 2;
    const int tig = lane & 3;

    // ldmatrix per-lane row/col selects
    const int lr = lane & 7;
    const int aRow = wm + lr + ((lane >> 3) & 1) * 8;   // + mi*16
    const int aK   = ((lane >> 4) & 1) * 8;             // + ks*16
    const int bRw  = wn + lr + ((lane >> 4) & 1) * 8;   // + pair*16
    const int bK   = ((lane >> 3) & 1) * 8;             // + ks*16

    float acc[4][4][4];
    #pragma unroll
    for (int mi = 0; mi < 4; mi++)
        #pragma unroll
        for (int ni = 0; ni < 4; ni++)
            #pragma unroll
            for (int r = 0; r < 4; r++) acc[mi][ni][r] = 0.f;

    // stage offsets in halves: A(s) = s*9216 ; B(s) = 27648 + s*9216
    auto load = [&](int chunk, int s) {
        int k0 = chunk * 64;
        #pragma unroll
        for (int it = 0; it < 4; it++) {
            int idx = tid + it * 256;
            int r = idx >> 3, cs = idx & 7;
            cp_async16(base + (uint32_t)(s * 9216 + r * 72 + cs * 8) * 2,
                       A + (size_t)(bRow + r) * lda + k0 + cs * 8);
        }
        #pragma unroll
        for (int it = 0; it < 4; it++) {
            int idx = tid + it * 256;
            int r = idx >> 3, cs = idx & 7;
            cp_async16(base + (uint32_t)(27648 + s * 9216 + r * 72 + cs * 8) * 2,
                       Bt + (size_t)(bCol + r) * ldb + k0 + cs * 8);
        }
    };

    const int nk = K >> 6;
    load(0, 0); cp_commit();
    if (nk > 1) { load(1, 1); cp_commit(); }

    for (int j = 0; j < nk; j++) {
        int s = j % 3;
        if (j + 1 < nk) cp_wait1(); else cp_wait0();
        __syncthreads();
        // issue next-next chunk's loads BEFORE compute (slot (j+2)%3 is free:
        // its last readers were iteration j-1, ordered by the barrier above)
        if (j + 2 < nk) { load(j + 2, (j + 2) % 3); cp_commit(); }

        uint32_t aBase = base + (uint32_t)(s * 9216 + aRow * 72 + aK) * 2;
        uint32_t bBase = base + (uint32_t)(27648 + s * 9216 + bRw * 72 + bK) * 2;
        #pragma unroll
        for (int ks = 0; ks < 4; ks++) {
            uint32_t af[4][4];
            #pragma unroll
            for (int mi = 0; mi < 4; mi++)
                ldsm4(af[mi][0], af[mi][1], af[mi][2], af[mi][3],
                      aBase + (uint32_t)(mi * 16 * 72 + ks * 16) * 2);
            uint32_t bf[4][2];
            ldsm4(bf[0][0], bf[0][1], bf[1][0], bf[1][1],
                  bBase + (uint32_t)(ks * 16) * 2);
            ldsm4(bf[2][0], bf[2][1], bf[3][0], bf[3][1],
                  bBase + (uint32_t)(16 * 72 + ks * 16) * 2);
            #pragma unroll
            for (int mi = 0; mi < 4; mi++)
                #pragma unroll
                for (int ni = 0; ni < 4; ni++)
                    mma16(acc[mi][ni], af[mi][0], af[mi][1], af[mi][2], af[mi][3],
                          bf[ni][0], bf[ni][1]);
        }
    }

    // epilogue
    #pragma unroll
    for (int mi = 0; mi < 4; mi++) {
        #pragma unroll
        for (int ni = 0; ni < 4; ni++) {
            int r0 = bRow + wm + mi * 16 + gid;
            int c0 = bCol + wn + ni * 8 + tig * 2;
            #pragma unroll
            for (int hi = 0; hi < 2; hi++) {
                int r = r0 + hi * 8;
                float e0 = acc[mi][ni][hi * 2 + 0];
                float e1 = acc[mi][ni][hi * 2 + 1];
                if (BIAS) { e0 += bias[c0]; e1 += bias[c0 + 1]; }
                if (GELU) { e0 = gelu_exact(e0); e1 = gelu_exact(e1); }
                if (RES) {
                    __half2 rv = *(const __half2*)(res + (size_t)r * ldres + c0);
                    e0 += __half2float(rv.x); e1 += __half2float(rv.y);
                }
                if (WF32) {
                    size_t idx = (size_t)r * M + c0;
                    *(float2*)(C + idx) = make_float2(e0, e1);
                }
                if (WF16) {
                    size_t idx = (size_t)r * ldch + c0;
                    *(__half2*)(Ch + idx) = __floats2half2_rn(e0, e1);
                }
            }
        }
    }
}

// ---------------------------------------------------------------------------
// Per-dim head-mixing attention (half q in, half out; q pre-scaled by 0.125)
// K/V from combined [NCUR, 1024] buffer: cols [0,512)=kc, [512,1024)=vc
// ---------------------------------------------------------------------------
__global__ void attn_kernel(const __half* __restrict__ q,
                            const float* __restrict__ kv,
                            const float* __restrict__ e,
                            __half* __restrict__ att) {
    int idx = blockIdx.x * blockDim.x + threadIdx.x;
    int d = idx & 63;
    int row = idx >> 6;          // bta
    int a = row & (AA - 1);
    int bt = row >> 9;
    int b = bt >> 4;
    const __half* qr = q + (size_t)row * ZZ;
    const float* kr = kv + (size_t)(b * AA + a) * (2 * ZZ);
    const float* er = e + (size_t)bt * ZZ;
    float qv[8], kvv[8], vv[8];
    #pragma unroll
    for (int h = 0; h < 8; h++) {
        int o = h * 64 + d;
        qv[h] = __half2float(qr[o]);
        kvv[h] = kr[o] + er[o];
        vv[h] = kr[ZZ + o];
    }
    __half* outr = att + (size_t)row * ZZ;
    #pragma unroll
    for (int i = 0; i < 8; i++) {
        float l[8], m = -1e30f;
        #pragma unroll
        for (int j = 0; j < 8; j++) { l[j] = qv[i] * kvv[j]; m = fmaxf(m, l[j]); }
        float s = 0.f, o = 0.f;
        #pragma unroll
        for (int j = 0; j < 8; j++) {
            float p = expf(l[j] - m);
            s += p;
            o += p * vv[j];
        }
        outr[i * 64 + d] = __float2half(o / s);
    }
}

// ---------------------------------------------------------------------------
// Gate scalar + z_mid LN, 128 threads/row.
// o is read as half from cat[:,0:512]; writes ONLY half z_mid (zmh).
// ---------------------------------------------------------------------------
__global__ void gate_zmid_kernel(const __half* __restrict__ hgate,
                                 const float* __restrict__ Wg2,
                                 const float* __restrict__ bg2,
                                 const float* __restrict__ zpred,
                                 const __half* __restrict__ cat,
                                 const float* __restrict__ g_lno,
                                 const float* __restrict__ b_lno,
                                 __half* __restrict__ zmidH) {
    __shared__ float sb[32];
    int row = blockIdx.x;
    int tid = threadIdx.x;
    const __half* hr = hgate + (size_t)row * ZZ;
    float p = 0.f;
    #pragma unroll
    for (int k = 0; k < 4; k++) {
        int c = tid + k * 128;
        p += __half2float(hr[c]) * Wg2[c];
    }
    float dot = blockSum128(p, sb);
    float g = 1.0f / (1.0f + expf(-(dot + bg2[0])));

    const float* zr = zpred + (size_t)row * ZZ;
    const __half* orow = cat + (size_t)row * (2 * ZZ);   // cols [0,512) = o
    float y[4];
    float s = 0.f;
    #pragma unroll
    for (int k = 0; k < 4; k++) {
        int c = tid + k * 128;
        y[k] = zr[c] + g * __half2float(orow[c]);
        s += y[k];
    }
    float mean = blockSum128(s, sb) * (1.0f / ZZ);
    float s2 = 0.f;
    #pragma unroll
    for (int k = 0; k < 4; k++) { float d = y[k] - mean; s2 += d * d; }
    float var = blockSum128(s2, sb) * (1.0f / ZZ);
    float rstd = rsqrtf(var + 1e-5f);
    __half* zmh = zmidH + (size_t)row * ZZ;
    #pragma unroll
    for (int k = 0; k < 4; k++) {
        int c = tid + k * 128;
        float v = (y[k] - mean) * rstd * g_lno[c] + b_lno[c];
        zmh[c] = __float2half(v);
    }
}

// ---------------------------------------------------------------------------
// Launch
// ---------------------------------------------------------------------------
extern "C" void kernel_launch(void* const* d_in, const int* in_sizes, int n_in,
                              void* d_out, int out_size) {
    const float* z_current = (const float*)d_in[0];
    const float* z_pred    = (const float*)d_in[1];
    const float* actions   = (const float*)d_in[2];
    const float* Wq        = (const float*)d_in[3];
    const float* Wk        = (const float*)d_in[4];
    const float* Wv        = (const float*)d_in[5];
    const float* We        = (const float*)d_in[6];
    const float* Wo        = (const float*)d_in[7];
    const float* g_lnq     = (const float*)d_in[8];
    const float* b_lnq     = (const float*)d_in[9];
    const float* g_lno     = (const float*)d_in[10];
    const float* b_lno     = (const float*)d_in[11];
    const float* W_ff1     = (const float*)d_in[12];
    const float* b_ff1     = (const float*)d_in[13];
    const float* W_ff2     = (const float*)d_in[14];
    const float* b_ff2     = (const float*)d_in[15];
    const float* W_edge    = (const float*)d_in[16];
    const float* b_edge    = (const float*)d_in[17];
    const float* Wg1       = (const float*)d_in[18];
    const float* bg1       = (const float*)d_in[19];
    const float* Wg2       = (const float*)d_in[20];
    const float* bg2       = (const float*)d_in[21];
    float* out = (float*)d_out;

    void *pkv, *pe;
    void *pqln, *pq, *patt, *pcat, *phg, *phzc, *phzm, *phhid, *phw;
    cudaGetSymbolAddress(&pkv,  d_kv);
    cudaGetSymbolAddress(&pe,   d_e);
    cudaGetSymbolAddress(&pqln, h_qln);
    cudaGetSymbolAddress(&pq,   h_q);
    cudaGetSymbolAddress(&patt, h_att);
    cudaGetSymbolAddress(&pcat, h_cat);
    cudaGetSymbolAddress(&phg,  h_hg);
    cudaGetSymbolAddress(&phzc, h_zc);
    cudaGetSymbolAddress(&phzm, h_zmid);
    cudaGetSymbolAddress(&phhid,h_hid);
    cudaGetSymbolAddress(&phw,  h_w);
    float* kv   = (float*)pkv;
    float* e    = (float*)pe;
    __half* qln = (__half*)pqln;
    __half* qh  = (__half*)pq;
    __half* att = (__half*)patt;
    __half* cat = (__half*)pcat;
    __half* hg  = (__half*)phg;
    __half* zc  = (__half*)phzc;
    __half* zmh = (__half*)phzm;
    __half* hid = (__half*)phhid;
    __half* wh  = (__half*)phw;

    cudaFuncSetAttribute(mm_h<false,false,false,false,true>,
                         cudaFuncAttributeMaxDynamicSharedMemorySize, MM_SMEM);
    cudaFuncSetAttribute(mm_h<false,false,false,true,false>,
                         cudaFuncAttributeMaxDynamicSharedMemorySize, MM_SMEM);
    cudaFuncSetAttribute(mm_h<true,true,false,false,true>,
                         cudaFuncAttributeMaxDynamicSharedMemorySize, MM_SMEM);
    cudaFuncSetAttribute(mm_h<true,false,true,true,false>,
                         cudaFuncAttributeMaxDynamicSharedMemorySize, MM_SMEM);

    // 0) fused prep: all weight transposes (+Wq scale) + z_current halfcopy
    prep_kernel<<<4608, 256>>>(Wq, Wk, Wv, Wo, Wg1, W_ff1, W_ff2,
                               z_current, wh, zc);
    // 1) LN(z_pred) -> qln (half) + cat[:,512:1024] = half(z_pred)
    ln_kernel<<<NROWS, 128>>>(z_pred, g_lnq, b_lnq, qln, cat);
    // 2) edge embedding
    edge_kernel<<<NBT, 64>>>(actions, W_edge, b_edge, We, e);
    // 3) q = qln @ (Wq/8) -> half
    mm_h<false,false,false,false,true><<<dim3(4, 256), 256, MM_SMEM>>>(
        qln, wh + OFF_WQ, nullptr, nullptr, nullptr, qh, ZZ, ZZ, ZZ, ZZ, ZZ, 0);
    // 4) [kc|vc] = zc @ [Wk|Wv] -> f32 combined (single M=1024 GEMM)
    mm_h<false,false,false,true,false><<<dim3(8, 16), 256, MM_SMEM>>>(
        zc, wh + OFF_WK, nullptr, nullptr, kv, nullptr, ZZ, 2*ZZ, ZZ, ZZ, 2*ZZ, 0);
    // 5) attention -> att (half)
    attn_kernel<<<(NROWS * 64) / 256, 256>>>(qh, kv, e, att);
    // 6) o = att @ Wo -> half ONLY, into cat[:,0:512]
    mm_h<false,false,false,false,true><<<dim3(4, 256), 256, MM_SMEM>>>(
        att, wh + OFF_WO, nullptr, nullptr, nullptr, cat, ZZ, ZZ, ZZ, ZZ, 2*ZZ, 0);
    // 7) gate hidden = gelu(cat @ Wg1 + bg1) -> hg (half)  [single K=1024 GEMM]
    mm_h<true,true,false,false,true><<<dim3(4, 256), 256, MM_SMEM>>>(
        cat, wh + OFF_WG1, bg1, nullptr, nullptr, hg, 2*ZZ, ZZ, 2*ZZ, 2*ZZ, ZZ, 0);
    // 8) gate scalar + z_mid -> zmh (half only; o read from cat)
    gate_zmid_kernel<<<NROWS, 128>>>(hg, Wg2, bg2, z_pred, cat, g_lno, b_lno, zmh);
    // 9) hidden = gelu(z_mid @ W_ff1 + b_ff1) -> half
    mm_h<true,true,false,false,true><<<dim3(16, 256), 256, MM_SMEM>>>(
        zmh, wh + OFF_FF1, b_ff1, nullptr, nullptr, hid, ZZ, 4*ZZ, ZZ, ZZ, 4*ZZ, 0);
    // 10) out = hidden @ W_ff2 + b_ff2 + half(z_mid) -> f32
    mm_h<true,false,true,true,false><<<dim3(4, 256), 256, MM_SMEM>>>(
        hid, wh + OFF_FF2, b_ff2, zmh, out, nullptr, 4*ZZ, ZZ, 4*ZZ, 4*ZZ, ZZ, ZZ);
}

// round 15
// speedup vs baseline: 1.0288x; 1.0288x over previous
#include <cuda_runtime.h>
#include <cuda_fp16.h>
#include <math.h>
#include <stdint.h>

// ---------------------------------------------------------------------------
// Problem constants
// ---------------------------------------------------------------------------
#define BB 4
#define TT 16
#define AA 512
#define ZZ 512
#define NFF 6
#define NROWS (BB*TT*AA)      // 32768
#define NCUR  (BB*AA)         // 2048
#define NBT   (BB*TT)         // 64

// ---------------------------------------------------------------------------
// Scratch (static device globals; no allocations allowed)
// ---------------------------------------------------------------------------
// fp32 scratch
__device__ float d_kv[NCUR*2*ZZ];        // [kc | vc] combined (stride 1024)
__device__ float d_e[NBT*ZZ];
__device__ float d_gdot[4*NROWS];        // per-ctaX partial gate dots
// fp16 scratch
__device__ __half h_qln[NROWS*ZZ];       // LN(z_pred) (Q GEMM input)
__device__ __half h_q[NROWS*ZZ];         // q projection, pre-scaled (attn input)
__device__ __half h_att[NROWS*ZZ];       // attention out (Wo input)
__device__ __half h_cat[NROWS*2*ZZ];     // [o | z_pred] concat (gate GEMM input)
__device__ __half h_zc[NCUR*ZZ];         // z_current half
__device__ __half h_zmid[NROWS*ZZ];      // z_mid half (FF1 input + FF2 residual)
__device__ __half h_hid[NROWS*4*ZZ];     // FF hidden half (FF2 input)
__device__ __half h_w[3670016];          // transposed half weights [M,K]

// offsets into h_w
#define OFF_WQ   0
#define OFF_WK   262144
#define OFF_WV   524288           // contiguous after WK -> combined [1024,512]
#define OFF_WO   786432
#define OFF_WG1  1048576          // [512, 1024]
#define OFF_FF1  1572864          // [2048, 512]
#define OFF_FF2  2621440          // [512, 2048]

// ---------------------------------------------------------------------------
// Helpers
// ---------------------------------------------------------------------------
__device__ __forceinline__ float gelu_exact(float x) {
    return 0.5f * x * (1.0f + erff(x * 0.70710678118654752f));
}
__device__ __forceinline__ uint32_t smem_u32(const void* p) {
    uint32_t a;
    asm("{ .reg .u64 t; cvta.to.shared.u64 t, %1; cvt.u32.u64 %0, t; }"
        : "=r"(a) : "l"(p));
    return a;
}
__device__ __forceinline__ void cp_async16(uint32_t s, const void* g) {
    asm volatile("cp.async.cg.shared.global [%0], [%1], 16;" :: "r"(s), "l"(g));
}
__device__ __forceinline__ void cp_commit() {
    asm volatile("cp.async.commit_group;");
}
__device__ __forceinline__ void cp_wait0() { asm volatile("cp.async.wait_group 0;"); }
__device__ __forceinline__ void cp_wait1() { asm volatile("cp.async.wait_group 1;"); }

// m16n8k16 fp16 MMA, fp32 accumulate
__device__ __forceinline__ void mma16(float c[4], uint32_t a0, uint32_t a1,
                                      uint32_t a2, uint32_t a3,
                                      uint32_t b0, uint32_t b1) {
    asm volatile(
        "mma.sync.aligned.m16n8k16.row.col.f32.f16.f16.f32 "
        "{%0,%1,%2,%3},{%4,%5,%6,%7},{%8,%9},{%0,%1,%2,%3};"
        : "+f"(c[0]), "+f"(c[1]), "+f"(c[2]), "+f"(c[3])
        : "r"(a0), "r"(a1), "r"(a2), "r"(a3), "r"(b0), "r"(b1));
}

__device__ __forceinline__ void ldsm4(uint32_t& r0, uint32_t& r1,
                                      uint32_t& r2, uint32_t& r3, uint32_t a) {
    asm volatile("ldmatrix.sync.aligned.m8n8.x4.shared.b16 {%0,%1,%2,%3}, [%4];"
        : "=r"(r0), "=r"(r1), "=r"(r2), "=r"(r3) : "r"(a));
}

__device__ __forceinline__ float blockSum128(float v, float* sb) {
    #pragma unroll
    for (int o = 16; o > 0; o >>= 1) v += __shfl_down_sync(0xffffffffu, v, o);
    int w = threadIdx.x >> 5;
    if ((threadIdx.x & 31) == 0) sb[w] = v;
    __syncthreads();
    if (threadIdx.x < 32) {
        float r = (threadIdx.x < 4) ? sb[threadIdx.x] : 0.0f;
        #pragma unroll
        for (int o = 2; o > 0; o >>= 1) r += __shfl_down_sync(0xffffffffu, r, o);
        if (threadIdx.x == 0) sb[0] = r;
    }
    __syncthreads();
    float out = sb[0];
    __syncthreads();
    return out;
}

// ---------------------------------------------------------------------------
// Fused prep: ALL weight transposes + z_current halfcopy in ONE launch.
// ---------------------------------------------------------------------------
__device__ __forceinline__ void tr_tile(const float* __restrict__ x,
                                        __half* __restrict__ y,
                                        int K, int M, int tile, float scale) {
    __shared__ float t[32][33];
    int tilesX = M >> 5;
    int m0 = (tile % tilesX) * 32;
    int k0 = (tile / tilesX) * 32;
    int tx = threadIdx.x & 31, ty = threadIdx.x >> 5;
    #pragma unroll
    for (int i = 0; i < 32; i += 8)
        t[ty + i][tx] = x[(size_t)(k0 + ty + i) * M + m0 + tx];
    __syncthreads();
    #pragma unroll
    for (int i = 0; i < 32; i += 8)
        y[(size_t)(m0 + ty + i) * K + k0 + tx] = __float2half(t[tx][ty + i] * scale);
}

__global__ void prep_kernel(const float* __restrict__ Wq,
                            const float* __restrict__ Wk,
                            const float* __restrict__ Wv,
                            const float* __restrict__ Wo,
                            const float* __restrict__ Wg1,
                            const float* __restrict__ Wff1,
                            const float* __restrict__ Wff2,
                            const float* __restrict__ zcur,
                            __half* __restrict__ wh,
                            __half* __restrict__ zc) {
    int b = blockIdx.x;
    if (b < 256)        tr_tile(Wq,   wh + OFF_WQ,  512,  512,  b,        0.125f);
    else if (b < 512)   tr_tile(Wk,   wh + OFF_WK,  512,  512,  b - 256,  1.0f);
    else if (b < 768)   tr_tile(Wv,   wh + OFF_WV,  512,  512,  b - 512,  1.0f);
    else if (b < 1024)  tr_tile(Wo,   wh + OFF_WO,  512,  512,  b - 768,  1.0f);
    else if (b < 1536)  tr_tile(Wg1,  wh + OFF_WG1, 1024, 512,  b - 1024, 1.0f);
    else if (b < 2560)  tr_tile(Wff1, wh + OFF_FF1, 512,  2048, b - 1536, 1.0f);
    else if (b < 3584)  tr_tile(Wff2, wh + OFF_FF2, 2048, 512,  b - 2560, 1.0f);
    else {
        int i = (b - 3584) * 256 + threadIdx.x;   // i < 262144 = (NCUR*ZZ)/4
        float4 v = ((const float4*)zcur)[i];
        __half2* yo = (__half2*)zc;
        yo[2 * i + 0] = __floats2half2_rn(v.x, v.y);
        yo[2 * i + 1] = __floats2half2_rn(v.z, v.w);
    }
}

// ---------------------------------------------------------------------------
// LayerNorm (per 512-wide row), 128 threads/row; writes half LN output AND
// deposits half(z_pred) into the concat buffer's upper 512 columns.
// ---------------------------------------------------------------------------
__global__ void ln_kernel(const float* __restrict__ x,
                          const float* __restrict__ g,
                          const float* __restrict__ b,
                          __half* __restrict__ y,
                          __half* __restrict__ cat) {
    __shared__ float sb[32];
    int row = blockIdx.x;
    int tid = threadIdx.x;
    const float* xr = x + (size_t)row * ZZ;
    float v[4];
    float s = 0.f;
    #pragma unroll
    for (int k = 0; k < 4; k++) { v[k] = xr[tid + k * 128]; s += v[k]; }
    float mean = blockSum128(s, sb) * (1.0f / ZZ);
    float s2 = 0.f;
    #pragma unroll
    for (int k = 0; k < 4; k++) { float d = v[k] - mean; s2 += d * d; }
    float var = blockSum128(s2, sb) * (1.0f / ZZ);
    float rstd = rsqrtf(var + 1e-5f);
    __half* yr = y + (size_t)row * ZZ;
    __half* cr = cat + (size_t)row * (2 * ZZ) + ZZ;
    #pragma unroll
    for (int k = 0; k < 4; k++) {
        int c = tid + k * 128;
        yr[c] = __float2half((v[k] - mean) * rstd * g[c] + b[c]);
        cr[c] = __float2half(v[k]);
    }
}

// ---------------------------------------------------------------------------
// Edge embedding: fourier(actions) @ W_edge + b_edge -> @ We   (64 rows)
// ---------------------------------------------------------------------------
__global__ void edge_kernel(const float* __restrict__ actions,
                            const float* __restrict__ W_edge,
                            const float* __restrict__ b_edge,
                            const float* __restrict__ We,
                            float* __restrict__ eout) {
    __shared__ float feats[38];
    __shared__ float hid[64];
    int bt = blockIdx.x;
    int tid = threadIdx.x;
    if (tid == 0) {
        float dx = actions[bt * 4 + 0];
        float dy = actions[bt * 4 + 1];
        float th = actions[bt * 4 + 2];
        feats[0] = sinf(th);
        feats[1] = cosf(th);
        #pragma unroll
        for (int k = 0; k < NFF; k++) {
            float f = 3.14159265358979323846f * (float)(1 << k);
            feats[2 + 6 * k + 0] = sinf(f * dx);
            feats[2 + 6 * k + 1] = cosf(f * dx);
            feats[2 + 6 * k + 2] = sinf(f * dy);
            feats[2 + 6 * k + 3] = cosf(f * dy);
            feats[2 + 6 * k + 4] = sinf(f * th);
            feats[2 + 6 * k + 5] = cosf(f * th);
        }
    }
    __syncthreads();
    float h = b_edge[tid];
    #pragma unroll
    for (int j = 0; j < 38; j++) h += feats[j] * W_edge[j * 64 + tid];
    hid[tid] = h;
    __syncthreads();
    #pragma unroll
    for (int c = 0; c < 8; c++) {
        int col = c * 64 + tid;
        float acc = 0.f;
        #pragma unroll
        for (int j = 0; j < 64; j++) acc += hid[j] * We[j * ZZ + col];
        eout[(size_t)bt * ZZ + col] = acc;
    }
}

// ---------------------------------------------------------------------------
// fp16 tensor-core GEMM: C[N,M] = A[N,K] @ Bt[M,K]^T  (A, Bt half; fp32 accum)
// 128x128x64 tiles, 2-stage cp.async, 8 warps of 64x32, mma m16n8k16, ldmatrix.
// Epilogue: BIAS, GELU, RES (half, ldres), WF32, WF16, GDOT (row-dot with Wg2
// into gdot[ctaX][row] -- deterministic smem reduction, no global stores).
// smem halves: As[2][128][72], Bs[2][128][72] -> 73728 B dynamic
// ---------------------------------------------------------------------------
#define MM_SMEM (4 * 9216 * 2)

template<bool BIAS, bool GELU, bool RES, bool WF32, bool WF16, bool GDOT>
__global__ void __launch_bounds__(256, 2)
mm_h(const __half* __restrict__ A, const __half* __restrict__ Bt,
     const float* __restrict__ bias, const __half* __restrict__ res,
     float* __restrict__ C, __half* __restrict__ Ch,
     const float* __restrict__ Wg2g, float* __restrict__ gdot,
     int K, int M, int lda, int ldb, int ldch, int ldres) {
    extern __shared__ __half smh[];
    const uint32_t base = smem_u32(smh);

    const int tid = threadIdx.x;
    const int lane = tid & 31;
    const int wid = tid >> 5;
    const int wm = (wid >> 2) * 64;
    const int wn = (wid & 3) * 32;
    const int bRow = blockIdx.y * 128;
    const int bCol = blockIdx.x * 128;
    const int gid = lane >> 2;
    const int tig = lane & 3;

    // ldmatrix per-lane row/col selects
    const int lr = lane & 7;
    const int aRow = wm + lr + ((lane >> 3) & 1) * 8;   // + mi*16
    const int aK   = ((lane >> 4) & 1) * 8;             // + ks*16
    const int bRw  = wn + lr + ((lane >> 4) & 1) * 8;   // + pair*16
    const int bK   = ((lane >> 3) & 1) * 8;             // + ks*16

    float acc[4][4][4];
    #pragma unroll
    for (int mi = 0; mi < 4; mi++)
        #pragma unroll
        for (int ni = 0; ni < 4; ni++)
            #pragma unroll
            for (int r = 0; r < 4; r++) acc[mi][ni][r] = 0.f;

    // stage offsets in halves: A(s) = s*9216 ; B(s) = 18432 + s*9216
    auto load = [&](int chunk, int s) {
        int k0 = chunk * 64;
        #pragma unroll
        for (int it = 0; it < 4; it++) {
            int idx = tid + it * 256;
            int r = idx >> 3, cs = idx & 7;
            cp_async16(base + (uint32_t)(s * 9216 + r * 72 + cs * 8) * 2,
                       A + (size_t)(bRow + r) * lda + k0 + cs * 8);
        }
        #pragma unroll
        for (int it = 0; it < 4; it++) {
            int idx = tid + it * 256;
            int r = idx >> 3, cs = idx & 7;
            cp_async16(base + (uint32_t)(18432 + s * 9216 + r * 72 + cs * 8) * 2,
                       Bt + (size_t)(bCol + r) * ldb + k0 + cs * 8);
        }
    };

    const int nk = K >> 6;
    load(0, 0); cp_commit();
    if (nk > 1) { load(1, 1); cp_commit(); }

    for (int j = 0; j < nk; j++) {
        int s = j & 1;
        if (j + 1 < nk) cp_wait1(); else cp_wait0();
        __syncthreads();

        uint32_t aBase = base + (uint32_t)(s * 9216 + aRow * 72 + aK) * 2;
        uint32_t bBase = base + (uint32_t)(18432 + s * 9216 + bRw * 72 + bK) * 2;
        #pragma unroll
        for (int ks = 0; ks < 4; ks++) {
            uint32_t af[4][4];
            #pragma unroll
            for (int mi = 0; mi < 4; mi++)
                ldsm4(af[mi][0], af[mi][1], af[mi][2], af[mi][3],
                      aBase + (uint32_t)(mi * 16 * 72 + ks * 16) * 2);
            uint32_t bf[4][2];
            ldsm4(bf[0][0], bf[0][1], bf[1][0], bf[1][1],
                  bBase + (uint32_t)(ks * 16) * 2);
            ldsm4(bf[2][0], bf[2][1], bf[3][0], bf[3][1],
                  bBase + (uint32_t)(16 * 72 + ks * 16) * 2);
            #pragma unroll
            for (int mi = 0; mi < 4; mi++)
                #pragma unroll
                for (int ni = 0; ni < 4; ni++)
                    mma16(acc[mi][ni], af[mi][0], af[mi][1], af[mi][2], af[mi][3],
                          bf[ni][0], bf[ni][1]);
        }
        __syncthreads();
        if (j + 2 < nk) { load(j + 2, s); cp_commit(); }
    }

    // per-thread row partials for GDOT (rows: mi x hi)
    float rowsum[4][2];
    if (GDOT) {
        #pragma unroll
        for (int mi = 0; mi < 4; mi++) { rowsum[mi][0] = 0.f; rowsum[mi][1] = 0.f; }
    }

    // epilogue
    #pragma unroll
    for (int mi = 0; mi < 4; mi++) {
        #pragma unroll
        for (int ni = 0; ni < 4; ni++) {
            int r0 = bRow + wm + mi * 16 + gid;
            int c0 = bCol + wn + ni * 8 + tig * 2;
            #pragma unroll
            for (int hi = 0; hi < 2; hi++) {
                int r = r0 + hi * 8;
                float e0 = acc[mi][ni][hi * 2 + 0];
                float e1 = acc[mi][ni][hi * 2 + 1];
                if (BIAS) { e0 += bias[c0]; e1 += bias[c0 + 1]; }
                if (GELU) { e0 = gelu_exact(e0); e1 = gelu_exact(e1); }
                if (RES) {
                    __half2 rv = *(const __half2*)(res + (size_t)r * ldres + c0);
                    e0 += __half2float(rv.x); e1 += __half2float(rv.y);
                }
                if (GDOT) {
                    rowsum[mi][hi] += e0 * Wg2g[c0] + e1 * Wg2g[c0 + 1];
                }
                if (WF32) {
                    size_t idx = (size_t)r * M + c0;
                    *(float2*)(C + idx) = make_float2(e0, e1);
                }
                if (WF16) {
                    size_t idx = (size_t)r * ldch + c0;
                    *(__half2*)(Ch + idx) = __floats2half2_rn(e0, e1);
                }
            }
        }
    }

    if (GDOT) {
        // reduce over the 4 tig lanes (same row), then combine the 4 wn warps
        // deterministically via smem, one partial per (ctaX,row).
        float* part = (float*)smh;            // [4][128]
        __syncthreads();                       // done reading smem tiles
        #pragma unroll
        for (int mi = 0; mi < 4; mi++)
            #pragma unroll
            for (int hi = 0; hi < 2; hi++) {
                float v = rowsum[mi][hi];
                v += __shfl_xor_sync(0xffffffffu, v, 1);
                v += __shfl_xor_sync(0xffffffffu, v, 2);
                if (tig == 0) {
                    int rl = wm + mi * 16 + gid + hi * 8;   // 0..127
                    part[(wid & 3) * 128 + rl] = v;
                }
            }
        __syncthreads();
        if (tid < 128) {
            float v = part[tid] + part[128 + tid] + part[256 + tid] + part[384 + tid];
            gdot[(size_t)blockIdx.x * (gridDim.y * 128) + bRow + tid] = v;
        }
    }
}

// ---------------------------------------------------------------------------
// Per-dim head-mixing attention (half q in, half out; q pre-scaled by 0.125)
// K/V from combined [NCUR, 1024] buffer: cols [0,512)=kc, [512,1024)=vc
// ---------------------------------------------------------------------------
__global__ void attn_kernel(const __half* __restrict__ q,
                            const float* __restrict__ kv,
                            const float* __restrict__ e,
                            __half* __restrict__ att) {
    int idx = blockIdx.x * blockDim.x + threadIdx.x;
    int d = idx & 63;
    int row = idx >> 6;          // bta
    int a = row & (AA - 1);
    int bt = row >> 9;
    int b = bt >> 4;
    const __half* qr = q + (size_t)row * ZZ;
    const float* kr = kv + (size_t)(b * AA + a) * (2 * ZZ);
    const float* er = e + (size_t)bt * ZZ;
    float qv[8], kvv[8], vv[8];
    #pragma unroll
    for (int h = 0; h < 8; h++) {
        int o = h * 64 + d;
        qv[h] = __half2float(qr[o]);
        kvv[h] = kr[o] + er[o];
        vv[h] = kr[ZZ + o];
    }
    __half* outr = att + (size_t)row * ZZ;
    #pragma unroll
    for (int i = 0; i < 8; i++) {
        float l[8], m = -1e30f;
        #pragma unroll
        for (int j = 0; j < 8; j++) { l[j] = qv[i] * kvv[j]; m = fmaxf(m, l[j]); }
        float s = 0.f, o = 0.f;
        #pragma unroll
        for (int j = 0; j < 8; j++) {
            float p = __expf(l[j] - m);
            s += p;
            o += p * vv[j];
        }
        outr[i * 64 + d] = __float2half(o / s);
    }
}

// ---------------------------------------------------------------------------
// Gate scalar + z_mid LN, 128 threads/row.
// Gate dot read from gdot[4][NROWS] (fixed order -> deterministic);
// o read as half from cat[:,0:512]; writes ONLY half z_mid (zmh).
// ---------------------------------------------------------------------------
__global__ void gate_zmid_kernel(const float* __restrict__ gdot,
                                 const float* __restrict__ bg2,
                                 const float* __restrict__ zpred,
                                 const __half* __restrict__ cat,
                                 const float* __restrict__ g_lno,
                                 const float* __restrict__ b_lno,
                                 __half* __restrict__ zmidH) {
    __shared__ float sb[32];
    int row = blockIdx.x;
    int tid = threadIdx.x;
    float dot = gdot[row] + gdot[NROWS + row] + gdot[2 * NROWS + row]
              + gdot[3 * NROWS + row];
    float g = 1.0f / (1.0f + expf(-(dot + bg2[0])));

    const float* zr = zpred + (size_t)row * ZZ;
    const __half* orow = cat + (size_t)row * (2 * ZZ);   // cols [0,512) = o
    float y[4];
    float s = 0.f;
    #pragma unroll
    for (int k = 0; k < 4; k++) {
        int c = tid + k * 128;
        y[k] = zr[c] + g * __half2float(orow[c]);
        s += y[k];
    }
    float mean = blockSum128(s, sb) * (1.0f / ZZ);
    float s2 = 0.f;
    #pragma unroll
    for (int k = 0; k < 4; k++) { float d = y[k] - mean; s2 += d * d; }
    float var = blockSum128(s2, sb) * (1.0f / ZZ);
    float rstd = rsqrtf(var + 1e-5f);
    __half* zmh = zmidH + (size_t)row * ZZ;
    #pragma unroll
    for (int k = 0; k < 4; k++) {
        int c = tid + k * 128;
        float v = (y[k] - mean) * rstd * g_lno[c] + b_lno[c];
        zmh[c] = __float2half(v);
    }
}

// ---------------------------------------------------------------------------
// Launch
// ---------------------------------------------------------------------------
extern "C" void kernel_launch(void* const* d_in, const int* in_sizes, int n_in,
                              void* d_out, int out_size) {
    const float* z_current = (const float*)d_in[0];
    const float* z_pred    = (const float*)d_in[1];
    const float* actions   = (const float*)d_in[2];
    const float* Wq        = (const float*)d_in[3];
    const float* Wk        = (const float*)d_in[4];
    const float* Wv        = (const float*)d_in[5];
    const float* We        = (const float*)d_in[6];
    const float* Wo        = (const float*)d_in[7];
    const float* g_lnq     = (const float*)d_in[8];
    const float* b_lnq     = (const float*)d_in[9];
    const float* g_lno     = (const float*)d_in[10];
    const float* b_lno     = (const float*)d_in[11];
    const float* W_ff1     = (const float*)d_in[12];
    const float* b_ff1     = (const float*)d_in[13];
    const float* W_ff2     = (const float*)d_in[14];
    const float* b_ff2     = (const float*)d_in[15];
    const float* W_edge    = (const float*)d_in[16];
    const float* b_edge    = (const float*)d_in[17];
    const float* Wg1       = (const float*)d_in[18];
    const float* bg1       = (const float*)d_in[19];
    const float* Wg2       = (const float*)d_in[20];
    const float* bg2       = (const float*)d_in[21];
    float* out = (float*)d_out;

    void *pkv, *pe, *pgd;
    void *pqln, *pq, *patt, *pcat, *phzc, *phzm, *phhid, *phw;
    cudaGetSymbolAddress(&pkv,  d_kv);
    cudaGetSymbolAddress(&pe,   d_e);
    cudaGetSymbolAddress(&pgd,  d_gdot);
    cudaGetSymbolAddress(&pqln, h_qln);
    cudaGetSymbolAddress(&pq,   h_q);
    cudaGetSymbolAddress(&patt, h_att);
    cudaGetSymbolAddress(&pcat, h_cat);
    cudaGetSymbolAddress(&phzc, h_zc);
    cudaGetSymbolAddress(&phzm, h_zmid);
    cudaGetSymbolAddress(&phhid,h_hid);
    cudaGetSymbolAddress(&phw,  h_w);
    float* kv   = (float*)pkv;
    float* e    = (float*)pe;
    float* gdot = (float*)pgd;
    __half* qln = (__half*)pqln;
    __half* qh  = (__half*)pq;
    __half* att = (__half*)patt;
    __half* cat = (__half*)pcat;
    __half* zc  = (__half*)phzc;
    __half* zmh = (__half*)phzm;
    __half* hid = (__half*)phhid;
    __half* wh  = (__half*)phw;

    cudaFuncSetAttribute(mm_h<false,false,false,false,true,false>,
                         cudaFuncAttributeMaxDynamicSharedMemorySize, MM_SMEM);
    cudaFuncSetAttribute(mm_h<false,false,false,true,false,false>,
                         cudaFuncAttributeMaxDynamicSharedMemorySize, MM_SMEM);
    cudaFuncSetAttribute(mm_h<true,true,false,false,false,true>,
                         cudaFuncAttributeMaxDynamicSharedMemorySize, MM_SMEM);
    cudaFuncSetAttribute(mm_h<true,true,false,false,true,false>,
                         cudaFuncAttributeMaxDynamicSharedMemorySize, MM_SMEM);
    cudaFuncSetAttribute(mm_h<true,false,true,true,false,false>,
                         cudaFuncAttributeMaxDynamicSharedMemorySize, MM_SMEM);

    // 0) fused prep: all weight transposes (+Wq scale) + z_current halfcopy
    prep_kernel<<<4608, 256>>>(Wq, Wk, Wv, Wo, Wg1, W_ff1, W_ff2,
                               z_current, wh, zc);
    // 1) LN(z_pred) -> qln (half) + cat[:,512:1024] = half(z_pred)
    ln_kernel<<<NROWS, 128>>>(z_pred, g_lnq, b_lnq, qln, cat);
    // 2) edge embedding
    edge_kernel<<<NBT, 64>>>(actions, W_edge, b_edge, We, e);
    // 3) q = qln @ (Wq/8) -> half
    mm_h<false,false,false,false,true,false><<<dim3(4, 256), 256, MM_SMEM>>>(
        qln, wh + OFF_WQ, nullptr, nullptr, nullptr, qh, nullptr, nullptr,
        ZZ, ZZ, ZZ, ZZ, ZZ, 0);
    // 4) [kc|vc] = zc @ [Wk|Wv] -> f32 combined (single M=1024 GEMM)
    mm_h<false,false,false,true,false,false><<<dim3(8, 16), 256, MM_SMEM>>>(
        zc, wh + OFF_WK, nullptr, nullptr, kv, nullptr, nullptr, nullptr,
        ZZ, 2*ZZ, ZZ, ZZ, 2*ZZ, 0);
    // 5) attention -> att (half)
    attn_kernel<<<(NROWS * 64) / 256, 256>>>(qh, kv, e, att);
    // 6) o = att @ Wo -> half ONLY, into cat[:,0:512]
    mm_h<false,false,false,false,true,false><<<dim3(4, 256), 256, MM_SMEM>>>(
        att, wh + OFF_WO, nullptr, nullptr, nullptr, cat, nullptr, nullptr,
        ZZ, ZZ, ZZ, ZZ, 2*ZZ, 0);
    // 7) gate: gelu(cat @ Wg1 + bg1) . Wg2 -> gdot partials (no hidden buffer)
    mm_h<true,true,false,false,false,true><<<dim3(4, 256), 256, MM_SMEM>>>(
        cat, wh + OFF_WG1, bg1, nullptr, nullptr, nullptr, Wg2, gdot,
        2*ZZ, ZZ, 2*ZZ, 2*ZZ, ZZ, 0);
    // 8) gate scalar + z_mid -> zmh (half; dot from gdot, o from cat)
    gate_zmid_kernel<<<NROWS, 128>>>(gdot, bg2, z_pred, cat, g_lno, b_lno, zmh);
    // 9) hidden = gelu(z_mid @ W_ff1 + b_ff1) -> half
    mm_h<true,true,false,false,true,false><<<dim3(16, 256), 256, MM_SMEM>>>(
        zmh, wh + OFF_FF1, b_ff1, nullptr, nullptr, hid, nullptr, nullptr,
        ZZ, 4*ZZ, ZZ, ZZ, 4*ZZ, 0);
    // 10) out = hidden @ W_ff2 + b_ff2 + half(z_mid) -> f32
    mm_h<true,false,true,true,false,false><<<dim3(4, 256), 256, MM_SMEM>>>(
        hid, wh + OFF_FF2, b_ff2, zmh, out, nullptr, nullptr, nullptr,
        4*ZZ, ZZ, 4*ZZ, 4*ZZ, ZZ, ZZ);
}

// round 16
// speedup vs baseline: 1.0566x; 1.0270x over previous
#include <cuda_runtime.h>
#include <cuda_fp16.h>
#include <math.h>
#include <stdint.h>

// ---------------------------------------------------------------------------
// Problem constants
// ---------------------------------------------------------------------------
#define BB 4
#define TT 16
#define AA 512
#define ZZ 512
#define NFF 6
#define NROWS (BB*TT*AA)      // 32768
#define NCUR  (BB*AA)         // 2048
#define NBT   (BB*TT)         // 64

// ---------------------------------------------------------------------------
// Scratch (static device globals; no allocations allowed)
// ---------------------------------------------------------------------------
// fp32 scratch
__device__ float d_kv[NCUR*2*ZZ];        // [kc | vc] combined (stride 1024)
__device__ float d_e[NBT*ZZ];
__device__ float d_gdot[4*NROWS];        // per-ctaX partial gate dots
// fp16 scratch
__device__ __half h_qln[NROWS*ZZ];       // LN(z_pred) (Q GEMM input)
__device__ __half h_q[NROWS*ZZ];         // q projection, pre-scaled (attn input)
__device__ __half h_att[NROWS*ZZ];       // attention out (Wo input)
__device__ __half h_cat[NROWS*2*ZZ];     // [o | z_pred] concat (gate GEMM input)
__device__ __half h_zc[NCUR*ZZ];         // z_current half
__device__ __half h_zmid[NROWS*ZZ];      // z_mid half (FF1 input + FF2 residual)
__device__ __half h_hid[NROWS*4*ZZ];     // FF hidden half (FF2 input)
__device__ __half h_w[3670016];          // transposed half weights [M,K]

// offsets into h_w
#define OFF_WQ   0
#define OFF_WK   262144
#define OFF_WV   524288           // contiguous after WK -> combined [1024,512]
#define OFF_WO   786432
#define OFF_WG1  1048576          // [512, 1024]
#define OFF_FF1  1572864          // [2048, 512]
#define OFF_FF2  2621440          // [512, 2048]

// ---------------------------------------------------------------------------
// Helpers
// ---------------------------------------------------------------------------
__device__ __forceinline__ float gelu_exact(float x) {
    return 0.5f * x * (1.0f + erff(x * 0.70710678118654752f));
}
__device__ __forceinline__ uint32_t smem_u32(const void* p) {
    uint32_t a;
    asm("{ .reg .u64 t; cvta.to.shared.u64 t, %1; cvt.u32.u64 %0, t; }"
        : "=r"(a) : "l"(p));
    return a;
}
__device__ __forceinline__ void cp_async16(uint32_t s, const void* g) {
    asm volatile("cp.async.cg.shared.global [%0], [%1], 16;" :: "r"(s), "l"(g));
}
__device__ __forceinline__ void cp_commit() {
    asm volatile("cp.async.commit_group;");
}
__device__ __forceinline__ void cp_wait0() { asm volatile("cp.async.wait_group 0;"); }
__device__ __forceinline__ void cp_wait1() { asm volatile("cp.async.wait_group 1;"); }

// m16n8k16 fp16 MMA, fp32 accumulate
__device__ __forceinline__ void mma16(float c[4], uint32_t a0, uint32_t a1,
                                      uint32_t a2, uint32_t a3,
                                      uint32_t b0, uint32_t b1) {
    asm volatile(
        "mma.sync.aligned.m16n8k16.row.col.f32.f16.f16.f32 "
        "{%0,%1,%2,%3},{%4,%5,%6,%7},{%8,%9},{%0,%1,%2,%3};"
        : "+f"(c[0]), "+f"(c[1]), "+f"(c[2]), "+f"(c[3])
        : "r"(a0), "r"(a1), "r"(a2), "r"(a3), "r"(b0), "r"(b1));
}

__device__ __forceinline__ void ldsm4(uint32_t& r0, uint32_t& r1,
                                      uint32_t& r2, uint32_t& r3, uint32_t a) {
    asm volatile("ldmatrix.sync.aligned.m8n8.x4.shared.b16 {%0,%1,%2,%3}, [%4];"
        : "=r"(r0), "=r"(r1), "=r"(r2), "=r"(r3) : "r"(a));
}

// block-wide sum over 256 threads, result broadcast
__device__ __forceinline__ float blockSum256(float v, float* sb) {
    #pragma unroll
    for (int o = 16; o > 0; o >>= 1) v += __shfl_down_sync(0xffffffffu, v, o);
    int w = threadIdx.x >> 5;
    if ((threadIdx.x & 31) == 0) sb[w] = v;
    __syncthreads();
    if (threadIdx.x < 32) {
        float r = (threadIdx.x < 8) ? sb[threadIdx.x] : 0.0f;
        #pragma unroll
        for (int o = 4; o > 0; o >>= 1) r += __shfl_down_sync(0xffffffffu, r, o);
        if (threadIdx.x == 0) sb[0] = r;
    }
    __syncthreads();
    float out = sb[0];
    __syncthreads();
    return out;
}

// block-wide sum over 128 threads (for gate_zmid), result broadcast
__device__ __forceinline__ float blockSum128(float v, float* sb) {
    #pragma unroll
    for (int o = 16; o > 0; o >>= 1) v += __shfl_down_sync(0xffffffffu, v, o);
    int w = threadIdx.x >> 5;
    if ((threadIdx.x & 31) == 0) sb[w] = v;
    __syncthreads();
    if (threadIdx.x < 32) {
        float r = (threadIdx.x < 4) ? sb[threadIdx.x] : 0.0f;
        #pragma unroll
        for (int o = 2; o > 0; o >>= 1) r += __shfl_down_sync(0xffffffffu, r, o);
        if (threadIdx.x == 0) sb[0] = r;
    }
    __syncthreads();
    float out = sb[0];
    __syncthreads();
    return out;
}

// ---------------------------------------------------------------------------
// prep_all: weight transposes + z_current halfcopy + LN(z_pred) + edge
// in ONE launch. 256 threads/block.
//   [0,4608)            transposes + halfcopy (as before)
//   [4608, 4608+32768)  LN row blocks (256 thr, 2 elems each)
//   [37376, 37440)      edge embedding (64 blocks)
// ---------------------------------------------------------------------------
#define PREP_BLKS  4608
#define LN_BLKS    NROWS
#define EDGE_BASE  (PREP_BLKS + LN_BLKS)          // 37376
#define ALL_BLKS   (EDGE_BASE + NBT)              // 37440

__device__ __forceinline__ void tr_tile(const float* __restrict__ x,
                                        __half* __restrict__ y,
                                        int K, int M, int tile, float scale) {
    __shared__ float t[32][33];
    int tilesX = M >> 5;
    int m0 = (tile % tilesX) * 32;
    int k0 = (tile / tilesX) * 32;
    int tx = threadIdx.x & 31, ty = threadIdx.x >> 5;
    #pragma unroll
    for (int i = 0; i < 32; i += 8)
        t[ty + i][tx] = x[(size_t)(k0 + ty + i) * M + m0 + tx];
    __syncthreads();
    #pragma unroll
    for (int i = 0; i < 32; i += 8)
        y[(size_t)(m0 + ty + i) * K + k0 + tx] = __float2half(t[tx][ty + i] * scale);
}

__global__ void prep_all(const float* __restrict__ Wq,
                         const float* __restrict__ Wk,
                         const float* __restrict__ Wv,
                         const float* __restrict__ Wo,
                         const float* __restrict__ Wg1,
                         const float* __restrict__ Wff1,
                         const float* __restrict__ Wff2,
                         const float* __restrict__ zcur,
                         const float* __restrict__ zpred,
                         const float* __restrict__ g_lnq,
                         const float* __restrict__ b_lnq,
                         const float* __restrict__ actions,
                         const float* __restrict__ W_edge,
                         const float* __restrict__ b_edge,
                         const float* __restrict__ We,
                         __half* __restrict__ wh,
                         __half* __restrict__ zc,
                         __half* __restrict__ qln,
                         __half* __restrict__ cat,
                         float* __restrict__ eout) {
    int b = blockIdx.x;
    int tid = threadIdx.x;
    if (b < PREP_BLKS) {
        if (b < 256)        tr_tile(Wq,   wh + OFF_WQ,  512,  512,  b,        0.125f);
        else if (b < 512)   tr_tile(Wk,   wh + OFF_WK,  512,  512,  b - 256,  1.0f);
        else if (b < 768)   tr_tile(Wv,   wh + OFF_WV,  512,  512,  b - 512,  1.0f);
        else if (b < 1024)  tr_tile(Wo,   wh + OFF_WO,  512,  512,  b - 768,  1.0f);
        else if (b < 1536)  tr_tile(Wg1,  wh + OFF_WG1, 1024, 512,  b - 1024, 1.0f);
        else if (b < 2560)  tr_tile(Wff1, wh + OFF_FF1, 512,  2048, b - 1536, 1.0f);
        else if (b < 3584)  tr_tile(Wff2, wh + OFF_FF2, 2048, 512,  b - 2560, 1.0f);
        else {
            int i = (b - 3584) * 256 + tid;   // i < 262144 = (NCUR*ZZ)/4
            float4 v = ((const float4*)zcur)[i];
            __half2* yo = (__half2*)zc;
            yo[2 * i + 0] = __floats2half2_rn(v.x, v.y);
            yo[2 * i + 1] = __floats2half2_rn(v.z, v.w);
        }
    } else if (b < EDGE_BASE) {
        // LayerNorm: one 512-wide row per block, 2 elems per thread
        __shared__ float sb[32];
        int row = b - PREP_BLKS;
        const float* xr = zpred + (size_t)row * ZZ;
        float v[2];
        float s = 0.f;
        #pragma unroll
        for (int k = 0; k < 2; k++) { v[k] = xr[tid + k * 256]; s += v[k]; }
        float mean = blockSum256(s, sb) * (1.0f / ZZ);
        float s2 = 0.f;
        #pragma unroll
        for (int k = 0; k < 2; k++) { float d = v[k] - mean; s2 += d * d; }
        float var = blockSum256(s2, sb) * (1.0f / ZZ);
        float rstd = rsqrtf(var + 1e-5f);
        __half* yr = qln + (size_t)row * ZZ;
        __half* cr = cat + (size_t)row * (2 * ZZ) + ZZ;
        #pragma unroll
        for (int k = 0; k < 2; k++) {
            int c = tid + k * 256;
            yr[c] = __float2half((v[k] - mean) * rstd * g_lnq[c] + b_lnq[c]);
            cr[c] = __float2half(v[k]);
        }
    } else {
        // edge embedding, one bt per block
        __shared__ float feats[38];
        __shared__ float hid[64];
        int bt = b - EDGE_BASE;
        if (tid == 0) {
            float dx = actions[bt * 4 + 0];
            float dy = actions[bt * 4 + 1];
            float th = actions[bt * 4 + 2];
            feats[0] = sinf(th);
            feats[1] = cosf(th);
            #pragma unroll
            for (int k = 0; k < NFF; k++) {
                float f = 3.14159265358979323846f * (float)(1 << k);
                feats[2 + 6 * k + 0] = sinf(f * dx);
                feats[2 + 6 * k + 1] = cosf(f * dx);
                feats[2 + 6 * k + 2] = sinf(f * dy);
                feats[2 + 6 * k + 3] = cosf(f * dy);
                feats[2 + 6 * k + 4] = sinf(f * th);
                feats[2 + 6 * k + 5] = cosf(f * th);
            }
        }
        __syncthreads();
        if (tid < 64) {
            float h = b_edge[tid];
            #pragma unroll
            for (int j = 0; j < 38; j++) h += feats[j] * W_edge[j * 64 + tid];
            hid[tid] = h;
        }
        __syncthreads();
        #pragma unroll
        for (int c = 0; c < 2; c++) {
            int col = c * 256 + tid;
            float acc = 0.f;
            #pragma unroll
            for (int j = 0; j < 64; j++) acc += hid[j] * We[j * ZZ + col];
            eout[(size_t)bt * ZZ + col] = acc;
        }
    }
}

// ---------------------------------------------------------------------------
// fp16 tensor-core GEMM: C[N,M] = A[N,K] @ Bt[M,K]^T  (A, Bt half; fp32 accum)
// 128x128x64 tiles, 2-stage cp.async, 8 warps of 64x32, mma m16n8k16, ldmatrix.
// Epilogue: BIAS, GELU, RES (half, ldres), WF32, WF16, GDOT.
// smem halves: As[2][128][72], Bs[2][128][72] -> 73728 B dynamic
// ---------------------------------------------------------------------------
#define MM_SMEM (4 * 9216 * 2)

template<bool BIAS, bool GELU, bool RES, bool WF32, bool WF16, bool GDOT>
__global__ void __launch_bounds__(256, 2)
mm_h(const __half* __restrict__ A, const __half* __restrict__ Bt,
     const float* __restrict__ bias, const __half* __restrict__ res,
     float* __restrict__ C, __half* __restrict__ Ch,
     const float* __restrict__ Wg2g, float* __restrict__ gdot,
     int K, int M, int lda, int ldb, int ldch, int ldres) {
    extern __shared__ __half smh[];
    const uint32_t base = smem_u32(smh);

    const int tid = threadIdx.x;
    const int lane = tid & 31;
    const int wid = tid >> 5;
    const int wm = (wid >> 2) * 64;
    const int wn = (wid & 3) * 32;
    const int bRow = blockIdx.y * 128;
    const int bCol = blockIdx.x * 128;
    const int gid = lane >> 2;
    const int tig = lane & 3;

    const int lr = lane & 7;
    const int aRow = wm + lr + ((lane >> 3) & 1) * 8;
    const int aK   = ((lane >> 4) & 1) * 8;
    const int bRw  = wn + lr + ((lane >> 4) & 1) * 8;
    const int bK   = ((lane >> 3) & 1) * 8;

    float acc[4][4][4];
    #pragma unroll
    for (int mi = 0; mi < 4; mi++)
        #pragma unroll
        for (int ni = 0; ni < 4; ni++)
            #pragma unroll
            for (int r = 0; r < 4; r++) acc[mi][ni][r] = 0.f;

    auto load = [&](int chunk, int s) {
        int k0 = chunk * 64;
        #pragma unroll
        for (int it = 0; it < 4; it++) {
            int idx = tid + it * 256;
            int r = idx >> 3, cs = idx & 7;
            cp_async16(base + (uint32_t)(s * 9216 + r * 72 + cs * 8) * 2,
                       A + (size_t)(bRow + r) * lda + k0 + cs * 8);
        }
        #pragma unroll
        for (int it = 0; it < 4; it++) {
            int idx = tid + it * 256;
            int r = idx >> 3, cs = idx & 7;
            cp_async16(base + (uint32_t)(18432 + s * 9216 + r * 72 + cs * 8) * 2,
                       Bt + (size_t)(bCol + r) * ldb + k0 + cs * 8);
        }
    };

    const int nk = K >> 6;
    load(0, 0); cp_commit();
    if (nk > 1) { load(1, 1); cp_commit(); }

    for (int j = 0; j < nk; j++) {
        int s = j & 1;
        if (j + 1 < nk) cp_wait1(); else cp_wait0();
        __syncthreads();

        uint32_t aBase = base + (uint32_t)(s * 9216 + aRow * 72 + aK) * 2;
        uint32_t bBase = base + (uint32_t)(18432 + s * 9216 + bRw * 72 + bK) * 2;
        #pragma unroll
        for (int ks = 0; ks < 4; ks++) {
            uint32_t af[4][4];
            #pragma unroll
            for (int mi = 0; mi < 4; mi++)
                ldsm4(af[mi][0], af[mi][1], af[mi][2], af[mi][3],
                      aBase + (uint32_t)(mi * 16 * 72 + ks * 16) * 2);
            uint32_t bf[4][2];
            ldsm4(bf[0][0], bf[0][1], bf[1][0], bf[1][1],
                  bBase + (uint32_t)(ks * 16) * 2);
            ldsm4(bf[2][0], bf[2][1], bf[3][0], bf[3][1],
                  bBase + (uint32_t)(16 * 72 + ks * 16) * 2);
            #pragma unroll
            for (int mi = 0; mi < 4; mi++)
                #pragma unroll
                for (int ni = 0; ni < 4; ni++)
                    mma16(acc[mi][ni], af[mi][0], af[mi][1], af[mi][2], af[mi][3],
                          bf[ni][0], bf[ni][1]);
        }
        __syncthreads();
        if (j + 2 < nk) { load(j + 2, s); cp_commit(); }
    }

    float rowsum[4][2];
    if (GDOT) {
        #pragma unroll
        for (int mi = 0; mi < 4; mi++) { rowsum[mi][0] = 0.f; rowsum[mi][1] = 0.f; }
    }

    #pragma unroll
    for (int mi = 0; mi < 4; mi++) {
        #pragma unroll
        for (int ni = 0; ni < 4; ni++) {
            int r0 = bRow + wm + mi * 16 + gid;
            int c0 = bCol + wn + ni * 8 + tig * 2;
            #pragma unroll
            for (int hi = 0; hi < 2; hi++) {
                int r = r0 + hi * 8;
                float e0 = acc[mi][ni][hi * 2 + 0];
                float e1 = acc[mi][ni][hi * 2 + 1];
                if (BIAS) { e0 += bias[c0]; e1 += bias[c0 + 1]; }
                if (GELU) { e0 = gelu_exact(e0); e1 = gelu_exact(e1); }
                if (RES) {
                    __half2 rv = *(const __half2*)(res + (size_t)r * ldres + c0);
                    e0 += __half2float(rv.x); e1 += __half2float(rv.y);
                }
                if (GDOT) {
                    rowsum[mi][hi] += e0 * Wg2g[c0] + e1 * Wg2g[c0 + 1];
                }
                if (WF32) {
                    size_t idx = (size_t)r * M + c0;
                    *(float2*)(C + idx) = make_float2(e0, e1);
                }
                if (WF16) {
                    size_t idx = (size_t)r * ldch + c0;
                    *(__half2*)(Ch + idx) = __floats2half2_rn(e0, e1);
                }
            }
        }
    }

    if (GDOT) {
        float* part = (float*)smh;            // [4][128]
        __syncthreads();
        #pragma unroll
        for (int mi = 0; mi < 4; mi++)
            #pragma unroll
            for (int hi = 0; hi < 2; hi++) {
                float v = rowsum[mi][hi];
                v += __shfl_xor_sync(0xffffffffu, v, 1);
                v += __shfl_xor_sync(0xffffffffu, v, 2);
                if (tig == 0) {
                    int rl = wm + mi * 16 + gid + hi * 8;
                    part[(wid & 3) * 128 + rl] = v;
                }
            }
        __syncthreads();
        if (tid < 128) {
            float v = part[tid] + part[128 + tid] + part[256 + tid] + part[384 + tid];
            gdot[(size_t)blockIdx.x * (gridDim.y * 128) + bRow + tid] = v;
        }
    }
}

// ---------------------------------------------------------------------------
// mm_qkv: Q projection (blocks [0,1024)) and K/V projection (blocks
// [1024,1152)) in ONE launch. Same mainloop as mm_h; runtime epilogue switch.
//   Q : qln[N=32768,512] @ WqT -> h_q (half, ld 512)
//   KV: zc [N=2048, 512] @ [Wk|Wv]T -> d_kv (f32, ld 1024)
// ---------------------------------------------------------------------------
__global__ void __launch_bounds__(256, 2)
mm_qkv(const __half* __restrict__ qln, const __half* __restrict__ zc,
       const __half* __restrict__ wh,
       __half* __restrict__ qh, float* __restrict__ kvout) {
    extern __shared__ __half smh[];
    const uint32_t base = smem_u32(smh);

    const int tid = threadIdx.x;
    const int lane = tid & 31;
    const int wid = tid >> 5;
    const int wm = (wid >> 2) * 64;
    const int wn = (wid & 3) * 32;

    const bool isQ = blockIdx.x < 1024;
    int bRow, bCol;
    const __half* A;
    const __half* Bt;
    if (isQ) {
        int b = blockIdx.x;
        bCol = (b & 3) * 128;
        bRow = (b >> 2) * 128;
        A = qln;
        Bt = wh + OFF_WQ;
    } else {
        int b = blockIdx.x - 1024;
        bCol = (b & 7) * 128;
        bRow = (b >> 3) * 128;
        A = zc;
        Bt = wh + OFF_WK;     // [Wk|Wv] combined [1024,512]
    }
    const int gid = lane >> 2;
    const int tig = lane & 3;
    const int lr = lane & 7;
    const int aRow = wm + lr + ((lane >> 3) & 1) * 8;
    const int aK   = ((lane >> 4) & 1) * 8;
    const int bRw  = wn + lr + ((lane >> 4) & 1) * 8;
    const int bK   = ((lane >> 3) & 1) * 8;

    float acc[4][4][4];
    #pragma unroll
    for (int mi = 0; mi < 4; mi++)
        #pragma unroll
        for (int ni = 0; ni < 4; ni++)
            #pragma unroll
            for (int r = 0; r < 4; r++) acc[mi][ni][r] = 0.f;

    auto load = [&](int chunk, int s) {
        int k0 = chunk * 64;
        #pragma unroll
        for (int it = 0; it < 4; it++) {
            int idx = tid + it * 256;
            int r = idx >> 3, cs = idx & 7;
            cp_async16(base + (uint32_t)(s * 9216 + r * 72 + cs * 8) * 2,
                       A + (size_t)(bRow + r) * 512 + k0 + cs * 8);
        }
        #pragma unroll
        for (int it = 0; it < 4; it++) {
            int idx = tid + it * 256;
            int r = idx >> 3, cs = idx & 7;
            cp_async16(base + (uint32_t)(18432 + s * 9216 + r * 72 + cs * 8) * 2,
                       Bt + (size_t)(bCol + r) * 512 + k0 + cs * 8);
        }
    };

    load(0, 0); cp_commit();
    load(1, 1); cp_commit();

    #pragma unroll 1
    for (int j = 0; j < 8; j++) {
        int s = j & 1;
        if (j + 1 < 8) cp_wait1(); else cp_wait0();
        __syncthreads();

        uint32_t aBase = base + (uint32_t)(s * 9216 + aRow * 72 + aK) * 2;
        uint32_t bBase = base + (uint32_t)(18432 + s * 9216 + bRw * 72 + bK) * 2;
        #pragma unroll
        for (int ks = 0; ks < 4; ks++) {
            uint32_t af[4][4];
            #pragma unroll
            for (int mi = 0; mi < 4; mi++)
                ldsm4(af[mi][0], af[mi][1], af[mi][2], af[mi][3],
                      aBase + (uint32_t)(mi * 16 * 72 + ks * 16) * 2);
            uint32_t bf[4][2];
            ldsm4(bf[0][0], bf[0][1], bf[1][0], bf[1][1],
                  bBase + (uint32_t)(ks * 16) * 2);
            ldsm4(bf[2][0], bf[2][1], bf[3][0], bf[3][1],
                  bBase + (uint32_t)(16 * 72 + ks * 16) * 2);
            #pragma unroll
            for (int mi = 0; mi < 4; mi++)
                #pragma unroll
                for (int ni = 0; ni < 4; ni++)
                    mma16(acc[mi][ni], af[mi][0], af[mi][1], af[mi][2], af[mi][3],
                          bf[ni][0], bf[ni][1]);
        }
        __syncthreads();
        if (j + 2 < 8) { load(j + 2, s); cp_commit(); }
    }

    #pragma unroll
    for (int mi = 0; mi < 4; mi++) {
        #pragma unroll
        for (int ni = 0; ni < 4; ni++) {
            int r0 = bRow + wm + mi * 16 + gid;
            int c0 = bCol + wn + ni * 8 + tig * 2;
            #pragma unroll
            for (int hi = 0; hi < 2; hi++) {
                int r = r0 + hi * 8;
                float e0 = acc[mi][ni][hi * 2 + 0];
                float e1 = acc[mi][ni][hi * 2 + 1];
                if (isQ) {
                    *(__half2*)(qh + (size_t)r * 512 + c0) =
                        __floats2half2_rn(e0, e1);
                } else {
                    *(float2*)(kvout + (size_t)r * 1024 + c0) =
                        make_float2(e0, e1);
                }
            }
        }
    }
}

// ---------------------------------------------------------------------------
// Per-dim head-mixing attention (half q in, half out; q pre-scaled by 0.125)
// K/V from combined [NCUR, 1024] buffer: cols [0,512)=kc, [512,1024)=vc
// ---------------------------------------------------------------------------
__global__ void attn_kernel(const __half* __restrict__ q,
                            const float* __restrict__ kv,
                            const float* __restrict__ e,
                            __half* __restrict__ att) {
    int idx = blockIdx.x * blockDim.x + threadIdx.x;
    int d = idx & 63;
    int row = idx >> 6;          // bta
    int a = row & (AA - 1);
    int bt = row >> 9;
    int b = bt >> 4;
    const __half* qr = q + (size_t)row * ZZ;
    const float* kr = kv + (size_t)(b * AA + a) * (2 * ZZ);
    const float* er = e + (size_t)bt * ZZ;
    float qv[8], kvv[8], vv[8];
    #pragma unroll
    for (int h = 0; h < 8; h++) {
        int o = h * 64 + d;
        qv[h] = __half2float(qr[o]);
        kvv[h] = kr[o] + er[o];
        vv[h] = kr[ZZ + o];
    }
    __half* outr = att + (size_t)row * ZZ;
    #pragma unroll
    for (int i = 0; i < 8; i++) {
        float l[8], m = -1e30f;
        #pragma unroll
        for (int j = 0; j < 8; j++) { l[j] = qv[i] * kvv[j]; m = fmaxf(m, l[j]); }
        float s = 0.f, o = 0.f;
        #pragma unroll
        for (int j = 0; j < 8; j++) {
            float p = __expf(l[j] - m);
            s += p;
            o += p * vv[j];
        }
        outr[i * 64 + d] = __float2half(o / s);
    }
}

// ---------------------------------------------------------------------------
// Gate scalar + z_mid LN, 128 threads/row.
// ---------------------------------------------------------------------------
__global__ void gate_zmid_kernel(const float* __restrict__ gdot,
                                 const float* __restrict__ bg2,
                                 const float* __restrict__ zpred,
                                 const __half* __restrict__ cat,
                                 const float* __restrict__ g_lno,
                                 const float* __restrict__ b_lno,
                                 __half* __restrict__ zmidH) {
    __shared__ float sb[32];
    int row = blockIdx.x;
    int tid = threadIdx.x;
    float dot = gdot[row] + gdot[NROWS + row] + gdot[2 * NROWS + row]
              + gdot[3 * NROWS + row];
    float g = 1.0f / (1.0f + expf(-(dot + bg2[0])));

    const float* zr = zpred + (size_t)row * ZZ;
    const __half* orow = cat + (size_t)row * (2 * ZZ);   // cols [0,512) = o
    float y[4];
    float s = 0.f;
    #pragma unroll
    for (int k = 0; k < 4; k++) {
        int c = tid + k * 128;
        y[k] = zr[c] + g * __half2float(orow[c]);
        s += y[k];
    }
    float mean = blockSum128(s, sb) * (1.0f / ZZ);
    float s2 = 0.f;
    #pragma unroll
    for (int k = 0; k < 4; k++) { float d = y[k] - mean; s2 += d * d; }
    float var = blockSum128(s2, sb) * (1.0f / ZZ);
    float rstd = rsqrtf(var + 1e-5f);
    __half* zmh = zmidH + (size_t)row * ZZ;
    #pragma unroll
    for (int k = 0; k < 4; k++) {
        int c = tid + k * 128;
        float v = (y[k] - mean) * rstd * g_lno[c] + b_lno[c];
        zmh[c] = __float2half(v);
    }
}

// ---------------------------------------------------------------------------
// Launch (8 nodes: prep_all, qkv, attn, Wo, gate, gate_zmid, FF1, FF2)
// ---------------------------------------------------------------------------
extern "C" void kernel_launch(void* const* d_in, const int* in_sizes, int n_in,
                              void* d_out, int out_size) {
    const float* z_current = (const float*)d_in[0];
    const float* z_pred    = (const float*)d_in[1];
    const float* actions   = (const float*)d_in[2];
    const float* Wq        = (const float*)d_in[3];
    const float* Wk        = (const float*)d_in[4];
    const float* Wv        = (const float*)d_in[5];
    const float* We        = (const float*)d_in[6];
    const float* Wo        = (const float*)d_in[7];
    const float* g_lnq     = (const float*)d_in[8];
    const float* b_lnq     = (const float*)d_in[9];
    const float* g_lno     = (const float*)d_in[10];
    const float* b_lno     = (const float*)d_in[11];
    const float* W_ff1     = (const float*)d_in[12];
    const float* b_ff1     = (const float*)d_in[13];
    const float* W_ff2     = (const float*)d_in[14];
    const float* b_ff2     = (const float*)d_in[15];
    const float* W_edge    = (const float*)d_in[16];
    const float* b_edge    = (const float*)d_in[17];
    const float* Wg1       = (const float*)d_in[18];
    const float* bg1       = (const float*)d_in[19];
    const float* Wg2       = (const float*)d_in[20];
    const float* bg2       = (const float*)d_in[21];
    float* out = (float*)d_out;

    void *pkv, *pe, *pgd;
    void *pqln, *pq, *patt, *pcat, *phzc, *phzm, *phhid, *phw;
    cudaGetSymbolAddress(&pkv,  d_kv);
    cudaGetSymbolAddress(&pe,   d_e);
    cudaGetSymbolAddress(&pgd,  d_gdot);
    cudaGetSymbolAddress(&pqln, h_qln);
    cudaGetSymbolAddress(&pq,   h_q);
    cudaGetSymbolAddress(&patt, h_att);
    cudaGetSymbolAddress(&pcat, h_cat);
    cudaGetSymbolAddress(&phzc, h_zc);
    cudaGetSymbolAddress(&phzm, h_zmid);
    cudaGetSymbolAddress(&phhid,h_hid);
    cudaGetSymbolAddress(&phw,  h_w);
    float* kv   = (float*)pkv;
    float* e    = (float*)pe;
    float* gdot = (float*)pgd;
    __half* qln = (__half*)pqln;
    __half* qh  = (__half*)pq;
    __half* att = (__half*)patt;
    __half* cat = (__half*)pcat;
    __half* zc  = (__half*)phzc;
    __half* zmh = (__half*)phzm;
    __half* hid = (__half*)phhid;
    __half* wh  = (__half*)phw;

    cudaFuncSetAttribute(mm_qkv,
                         cudaFuncAttributeMaxDynamicSharedMemorySize, MM_SMEM);
    cudaFuncSetAttribute(mm_h<false,false,false,false,true,false>,
                         cudaFuncAttributeMaxDynamicSharedMemorySize, MM_SMEM);
    cudaFuncSetAttribute(mm_h<true,true,false,false,false,true>,
                         cudaFuncAttributeMaxDynamicSharedMemorySize, MM_SMEM);
    cudaFuncSetAttribute(mm_h<true,true,false,false,true,false>,
                         cudaFuncAttributeMaxDynamicSharedMemorySize, MM_SMEM);
    cudaFuncSetAttribute(mm_h<true,false,true,true,false,false>,
                         cudaFuncAttributeMaxDynamicSharedMemorySize, MM_SMEM);

    // 1) all input-only prep: transposes + halfcopy + LN + edge
    prep_all<<<ALL_BLKS, 256>>>(Wq, Wk, Wv, Wo, Wg1, W_ff1, W_ff2,
                                z_current, z_pred, g_lnq, b_lnq,
                                actions, W_edge, b_edge, We,
                                wh, zc, qln, cat, e);
    // 2) Q + K/V projections in one launch
    mm_qkv<<<1152, 256, MM_SMEM>>>(qln, zc, wh, qh, kv);
    // 3) attention -> att (half)
    attn_kernel<<<(NROWS * 64) / 256, 256>>>(qh, kv, e, att);
    // 4) o = att @ Wo -> half into cat[:,0:512]
    mm_h<false,false,false,false,true,false><<<dim3(4, 256), 256, MM_SMEM>>>(
        att, wh + OFF_WO, nullptr, nullptr, nullptr, cat, nullptr, nullptr,
        ZZ, ZZ, ZZ, ZZ, 2*ZZ, 0);
    // 5) gate: gelu(cat @ Wg1 + bg1) . Wg2 -> gdot partials
    mm_h<true,true,false,false,false,true><<<dim3(4, 256), 256, MM_SMEM>>>(
        cat, wh + OFF_WG1, bg1, nullptr, nullptr, nullptr, Wg2, gdot,
        2*ZZ, ZZ, 2*ZZ, 2*ZZ, ZZ, 0);
    // 6) gate scalar + z_mid -> zmh
    gate_zmid_kernel<<<NROWS, 128>>>(gdot, bg2, z_pred, cat, g_lno, b_lno, zmh);
    // 7) hidden = gelu(z_mid @ W_ff1 + b_ff1) -> half
    mm_h<true,true,false,false,true,false><<<dim3(16, 256), 256, MM_SMEM>>>(
        zmh, wh + OFF_FF1, b_ff1, nullptr, nullptr, hid, nullptr, nullptr,
        ZZ, 4*ZZ, ZZ, ZZ, 4*ZZ, 0);
    // 8) out = hidden @ W_ff2 + b_ff2 + half(z_mid) -> f32
    mm_h<true,false,true,true,false,false><<<dim3(4, 256), 256, MM_SMEM>>>(
        hid, wh + OFF_FF2, b_ff2, zmh, out, nullptr, nullptr, nullptr,
        4*ZZ, ZZ, 4*ZZ, 4*ZZ, ZZ, ZZ);
}

// round 17
// speedup vs baseline: 1.0615x; 1.0047x over previous
#include <cuda_runtime.h>
#include <cuda_fp16.h>
#include <math.h>
#include <stdint.h>

// ---------------------------------------------------------------------------
// Problem constants
// ---------------------------------------------------------------------------
#define BB 4
#define TT 16
#define AA 512
#define ZZ 512
#define NFF 6
#define NROWS (BB*TT*AA)      // 32768
#define NCUR  (BB*AA)         // 2048
#define NBT   (BB*TT)         // 64

// ---------------------------------------------------------------------------
// Scratch (static device globals; no allocations allowed)
// ---------------------------------------------------------------------------
__device__ float d_gdot[4*NROWS];        // per-ctaX partial gate dots
// fp16 scratch
__device__ __half h_kv[NCUR*2*ZZ];       // [kc | vc] combined half (stride 1024)
__device__ __half h_e[NBT*ZZ];           // edge embedding (half)
__device__ __half h_qln[NROWS*ZZ];       // LN(z_pred) (Q GEMM input)
__device__ __half h_q[NROWS*ZZ];         // q projection, pre-scaled (attn input)
__device__ __half h_att[NROWS*ZZ];       // attention out (Wo input)
__device__ __half h_cat[NROWS*2*ZZ];     // [o | z_pred] concat (gate GEMM input)
__device__ __half h_zc[NCUR*ZZ];         // z_current half
__device__ __half h_zmid[NROWS*ZZ];      // z_mid half (FF1 input + FF2 residual)
__device__ __half h_hid[NROWS*4*ZZ];     // FF hidden half (FF2 input)
__device__ __half h_w[3670016];          // transposed half weights [M,K]

// offsets into h_w
#define OFF_WQ   0
#define OFF_WK   262144
#define OFF_WV   524288           // contiguous after WK -> combined [1024,512]
#define OFF_WO   786432
#define OFF_WG1  1048576          // [512, 1024]
#define OFF_FF1  1572864          // [2048, 512]
#define OFF_FF2  2621440          // [512, 2048]

// ---------------------------------------------------------------------------
// Helpers
// ---------------------------------------------------------------------------
__device__ __forceinline__ float gelu_exact(float x) {
    return 0.5f * x * (1.0f + erff(x * 0.70710678118654752f));
}
__device__ __forceinline__ uint32_t smem_u32(const void* p) {
    uint32_t a;
    asm("{ .reg .u64 t; cvta.to.shared.u64 t, %1; cvt.u32.u64 %0, t; }"
        : "=r"(a) : "l"(p));
    return a;
}
__device__ __forceinline__ void cp_async16(uint32_t s, const void* g) {
    asm volatile("cp.async.cg.shared.global [%0], [%1], 16;" :: "r"(s), "l"(g));
}
__device__ __forceinline__ void cp_commit() {
    asm volatile("cp.async.commit_group;");
}
__device__ __forceinline__ void cp_wait0() { asm volatile("cp.async.wait_group 0;"); }
__device__ __forceinline__ void cp_wait1() { asm volatile("cp.async.wait_group 1;"); }

// m16n8k16 fp16 MMA, fp32 accumulate
__device__ __forceinline__ void mma16(float c[4], uint32_t a0, uint32_t a1,
                                      uint32_t a2, uint32_t a3,
                                      uint32_t b0, uint32_t b1) {
    asm volatile(
        "mma.sync.aligned.m16n8k16.row.col.f32.f16.f16.f32 "
        "{%0,%1,%2,%3},{%4,%5,%6,%7},{%8,%9},{%0,%1,%2,%3};"
        : "+f"(c[0]), "+f"(c[1]), "+f"(c[2]), "+f"(c[3])
        : "r"(a0), "r"(a1), "r"(a2), "r"(a3), "r"(b0), "r"(b1));
}

__device__ __forceinline__ void ldsm4(uint32_t& r0, uint32_t& r1,
                                      uint32_t& r2, uint32_t& r3, uint32_t a) {
    asm volatile("ldmatrix.sync.aligned.m8n8.x4.shared.b16 {%0,%1,%2,%3}, [%4];"
        : "=r"(r0), "=r"(r1), "=r"(r2), "=r"(r3) : "r"(a));
}

// block-wide sum over 256 threads, result broadcast
__device__ __forceinline__ float blockSum256(float v, float* sb) {
    #pragma unroll
    for (int o = 16; o > 0; o >>= 1) v += __shfl_down_sync(0xffffffffu, v, o);
    int w = threadIdx.x >> 5;
    if ((threadIdx.x & 31) == 0) sb[w] = v;
    __syncthreads();
    if (threadIdx.x < 32) {
        float r = (threadIdx.x < 8) ? sb[threadIdx.x] : 0.0f;
        #pragma unroll
        for (int o = 4; o > 0; o >>= 1) r += __shfl_down_sync(0xffffffffu, r, o);
        if (threadIdx.x == 0) sb[0] = r;
    }
    __syncthreads();
    float out = sb[0];
    __syncthreads();
    return out;
}

// block-wide sum over 128 threads, result broadcast
__device__ __forceinline__ float blockSum128(float v, float* sb) {
    #pragma unroll
    for (int o = 16; o > 0; o >>= 1) v += __shfl_down_sync(0xffffffffu, v, o);
    int w = threadIdx.x >> 5;
    if ((threadIdx.x & 31) == 0) sb[w] = v;
    __syncthreads();
    if (threadIdx.x < 32) {
        float r = (threadIdx.x < 4) ? sb[threadIdx.x] : 0.0f;
        #pragma unroll
        for (int o = 2; o > 0; o >>= 1) r += __shfl_down_sync(0xffffffffu, r, o);
        if (threadIdx.x == 0) sb[0] = r;
    }
    __syncthreads();
    float out = sb[0];
    __syncthreads();
    return out;
}

// ---------------------------------------------------------------------------
// prep_all: weight transposes + z_current halfcopy + LN(z_pred) + edge
// ---------------------------------------------------------------------------
#define PREP_BLKS  4608
#define LN_BLKS    NROWS
#define EDGE_BASE  (PREP_BLKS + LN_BLKS)          // 37376
#define ALL_BLKS   (EDGE_BASE + NBT)              // 37440

__device__ __forceinline__ void tr_tile(const float* __restrict__ x,
                                        __half* __restrict__ y,
                                        int K, int M, int tile, float scale) {
    __shared__ float t[32][33];
    int tilesX = M >> 5;
    int m0 = (tile % tilesX) * 32;
    int k0 = (tile / tilesX) * 32;
    int tx = threadIdx.x & 31, ty = threadIdx.x >> 5;
    #pragma unroll
    for (int i = 0; i < 32; i += 8)
        t[ty + i][tx] = x[(size_t)(k0 + ty + i) * M + m0 + tx];
    __syncthreads();
    #pragma unroll
    for (int i = 0; i < 32; i += 8)
        y[(size_t)(m0 + ty + i) * K + k0 + tx] = __float2half(t[tx][ty + i] * scale);
}

__global__ void prep_all(const float* __restrict__ Wq,
                         const float* __restrict__ Wk,
                         const float* __restrict__ Wv,
                         const float* __restrict__ Wo,
                         const float* __restrict__ Wg1,
                         const float* __restrict__ Wff1,
                         const float* __restrict__ Wff2,
                         const float* __restrict__ zcur,
                         const float* __restrict__ zpred,
                         const float* __restrict__ g_lnq,
                         const float* __restrict__ b_lnq,
                         const float* __restrict__ actions,
                         const float* __restrict__ W_edge,
                         const float* __restrict__ b_edge,
                         const float* __restrict__ We,
                         __half* __restrict__ wh,
                         __half* __restrict__ zc,
                         __half* __restrict__ qln,
                         __half* __restrict__ cat,
                         __half* __restrict__ eout) {
    int b = blockIdx.x;
    int tid = threadIdx.x;
    if (b < PREP_BLKS) {
        if (b < 256)        tr_tile(Wq,   wh + OFF_WQ,  512,  512,  b,        0.125f);
        else if (b < 512)   tr_tile(Wk,   wh + OFF_WK,  512,  512,  b - 256,  1.0f);
        else if (b < 768)   tr_tile(Wv,   wh + OFF_WV,  512,  512,  b - 512,  1.0f);
        else if (b < 1024)  tr_tile(Wo,   wh + OFF_WO,  512,  512,  b - 768,  1.0f);
        else if (b < 1536)  tr_tile(Wg1,  wh + OFF_WG1, 1024, 512,  b - 1024, 1.0f);
        else if (b < 2560)  tr_tile(Wff1, wh + OFF_FF1, 512,  2048, b - 1536, 1.0f);
        else if (b < 3584)  tr_tile(Wff2, wh + OFF_FF2, 2048, 512,  b - 2560, 1.0f);
        else {
            int i = (b - 3584) * 256 + tid;   // i < 262144 = (NCUR*ZZ)/4
            float4 v = ((const float4*)zcur)[i];
            __half2* yo = (__half2*)zc;
            yo[2 * i + 0] = __floats2half2_rn(v.x, v.y);
            yo[2 * i + 1] = __floats2half2_rn(v.z, v.w);
        }
    } else if (b < EDGE_BASE) {
        __shared__ float sb[32];
        int row = b - PREP_BLKS;
        const float* xr = zpred + (size_t)row * ZZ;
        float v[2];
        float s = 0.f;
        #pragma unroll
        for (int k = 0; k < 2; k++) { v[k] = xr[tid + k * 256]; s += v[k]; }
        float mean = blockSum256(s, sb) * (1.0f / ZZ);
        float s2 = 0.f;
        #pragma unroll
        for (int k = 0; k < 2; k++) { float d = v[k] - mean; s2 += d * d; }
        float var = blockSum256(s2, sb) * (1.0f / ZZ);
        float rstd = rsqrtf(var + 1e-5f);
        __half* yr = qln + (size_t)row * ZZ;
        __half* cr = cat + (size_t)row * (2 * ZZ) + ZZ;
        #pragma unroll
        for (int k = 0; k < 2; k++) {
            int c = tid + k * 256;
            yr[c] = __float2half((v[k] - mean) * rstd * g_lnq[c] + b_lnq[c]);
            cr[c] = __float2half(v[k]);
        }
    } else {
        __shared__ float feats[38];
        __shared__ float hid[64];
        int bt = b - EDGE_BASE;
        if (tid == 0) {
            float dx = actions[bt * 4 + 0];
            float dy = actions[bt * 4 + 1];
            float th = actions[bt * 4 + 2];
            feats[0] = sinf(th);
            feats[1] = cosf(th);
            #pragma unroll
            for (int k = 0; k < NFF; k++) {
                float f = 3.14159265358979323846f * (float)(1 << k);
                feats[2 + 6 * k + 0] = sinf(f * dx);
                feats[2 + 6 * k + 1] = cosf(f * dx);
                feats[2 + 6 * k + 2] = sinf(f * dy);
                feats[2 + 6 * k + 3] = cosf(f * dy);
                feats[2 + 6 * k + 4] = sinf(f * th);
                feats[2 + 6 * k + 5] = cosf(f * th);
            }
        }
        __syncthreads();
        if (tid < 64) {
            float h = b_edge[tid];
            #pragma unroll
            for (int j = 0; j < 38; j++) h += feats[j] * W_edge[j * 64 + tid];
            hid[tid] = h;
        }
        __syncthreads();
        #pragma unroll
        for (int c = 0; c < 2; c++) {
            int col = c * 256 + tid;
            float acc = 0.f;
            #pragma unroll
            for (int j = 0; j < 64; j++) acc += hid[j] * We[j * ZZ + col];
            eout[(size_t)bt * ZZ + col] = __float2half(acc);
        }
    }
}

// ---------------------------------------------------------------------------
// fp16 tensor-core GEMM (proven R13 config)
// ---------------------------------------------------------------------------
#define MM_SMEM (4 * 9216 * 2)

template<bool BIAS, bool GELU, bool RES, bool WF32, bool WF16, bool GDOT>
__global__ void __launch_bounds__(256, 2)
mm_h(const __half* __restrict__ A, const __half* __restrict__ Bt,
     const float* __restrict__ bias, const __half* __restrict__ res,
     float* __restrict__ C, __half* __restrict__ Ch,
     const float* __restrict__ Wg2g, float* __restrict__ gdot,
     int K, int M, int lda, int ldb, int ldch, int ldres) {
    extern __shared__ __half smh[];
    const uint32_t base = smem_u32(smh);

    const int tid = threadIdx.x;
    const int lane = tid & 31;
    const int wid = tid >> 5;
    const int wm = (wid >> 2) * 64;
    const int wn = (wid & 3) * 32;
    const int bRow = blockIdx.y * 128;
    const int bCol = blockIdx.x * 128;
    const int gid = lane >> 2;
    const int tig = lane & 3;

    const int lr = lane & 7;
    const int aRow = wm + lr + ((lane >> 3) & 1) * 8;
    const int aK   = ((lane >> 4) & 1) * 8;
    const int bRw  = wn + lr + ((lane >> 4) & 1) * 8;
    const int bK   = ((lane >> 3) & 1) * 8;

    float acc[4][4][4];
    #pragma unroll
    for (int mi = 0; mi < 4; mi++)
        #pragma unroll
        for (int ni = 0; ni < 4; ni++)
            #pragma unroll
            for (int r = 0; r < 4; r++) acc[mi][ni][r] = 0.f;

    auto load = [&](int chunk, int s) {
        int k0 = chunk * 64;
        #pragma unroll
        for (int it = 0; it < 4; it++) {
            int idx = tid + it * 256;
            int r = idx >> 3, cs = idx & 7;
            cp_async16(base + (uint32_t)(s * 9216 + r * 72 + cs * 8) * 2,
                       A + (size_t)(bRow + r) * lda + k0 + cs * 8);
        }
        #pragma unroll
        for (int it = 0; it < 4; it++) {
            int idx = tid + it * 256;
            int r = idx >> 3, cs = idx & 7;
            cp_async16(base + (uint32_t)(18432 + s * 9216 + r * 72 + cs * 8) * 2,
                       Bt + (size_t)(bCol + r) * ldb + k0 + cs * 8);
        }
    };

    const int nk = K >> 6;
    load(0, 0); cp_commit();
    if (nk > 1) { load(1, 1); cp_commit(); }

    for (int j = 0; j < nk; j++) {
        int s = j & 1;
        if (j + 1 < nk) cp_wait1(); else cp_wait0();
        __syncthreads();

        uint32_t aBase = base + (uint32_t)(s * 9216 + aRow * 72 + aK) * 2;
        uint32_t bBase = base + (uint32_t)(18432 + s * 9216 + bRw * 72 + bK) * 2;
        #pragma unroll
        for (int ks = 0; ks < 4; ks++) {
            uint32_t af[4][4];
            #pragma unroll
            for (int mi = 0; mi < 4; mi++)
                ldsm4(af[mi][0], af[mi][1], af[mi][2], af[mi][3],
                      aBase + (uint32_t)(mi * 16 * 72 + ks * 16) * 2);
            uint32_t bf[4][2];
            ldsm4(bf[0][0], bf[0][1], bf[1][0], bf[1][1],
                  bBase + (uint32_t)(ks * 16) * 2);
            ldsm4(bf[2][0], bf[2][1], bf[3][0], bf[3][1],
                  bBase + (uint32_t)(16 * 72 + ks * 16) * 2);
            #pragma unroll
            for (int mi = 0; mi < 4; mi++)
                #pragma unroll
                for (int ni = 0; ni < 4; ni++)
                    mma16(acc[mi][ni], af[mi][0], af[mi][1], af[mi][2], af[mi][3],
                          bf[ni][0], bf[ni][1]);
        }
        __syncthreads();
        if (j + 2 < nk) { load(j + 2, s); cp_commit(); }
    }

    float rowsum[4][2];
    if (GDOT) {
        #pragma unroll
        for (int mi = 0; mi < 4; mi++) { rowsum[mi][0] = 0.f; rowsum[mi][1] = 0.f; }
    }

    #pragma unroll
    for (int mi = 0; mi < 4; mi++) {
        #pragma unroll
        for (int ni = 0; ni < 4; ni++) {
            int r0 = bRow + wm + mi * 16 + gid;
            int c0 = bCol + wn + ni * 8 + tig * 2;
            #pragma unroll
            for (int hi = 0; hi < 2; hi++) {
                int r = r0 + hi * 8;
                float e0 = acc[mi][ni][hi * 2 + 0];
                float e1 = acc[mi][ni][hi * 2 + 1];
                if (BIAS) { e0 += bias[c0]; e1 += bias[c0 + 1]; }
                if (GELU) { e0 = gelu_exact(e0); e1 = gelu_exact(e1); }
                if (RES) {
                    __half2 rv = *(const __half2*)(res + (size_t)r * ldres + c0);
                    e0 += __half2float(rv.x); e1 += __half2float(rv.y);
                }
                if (GDOT) {
                    rowsum[mi][hi] += e0 * Wg2g[c0] + e1 * Wg2g[c0 + 1];
                }
                if (WF32) {
                    size_t idx = (size_t)r * M + c0;
                    *(float2*)(C + idx) = make_float2(e0, e1);
                }
                if (WF16) {
                    size_t idx = (size_t)r * ldch + c0;
                    *(__half2*)(Ch + idx) = __floats2half2_rn(e0, e1);
                }
            }
        }
    }

    if (GDOT) {
        float* part = (float*)smh;            // [4][128]
        __syncthreads();
        #pragma unroll
        for (int mi = 0; mi < 4; mi++)
            #pragma unroll
            for (int hi = 0; hi < 2; hi++) {
                float v = rowsum[mi][hi];
                v += __shfl_xor_sync(0xffffffffu, v, 1);
                v += __shfl_xor_sync(0xffffffffu, v, 2);
                if (tig == 0) {
                    int rl = wm + mi * 16 + gid + hi * 8;
                    part[(wid & 3) * 128 + rl] = v;
                }
            }
        __syncthreads();
        if (tid < 128) {
            float v = part[tid] + part[128 + tid] + part[256 + tid] + part[384 + tid];
            gdot[(size_t)blockIdx.x * (gridDim.y * 128) + bRow + tid] = v;
        }
    }
}

// ---------------------------------------------------------------------------
// mm_qkv: Q projection (blocks [0,1024)) and K/V projection (blocks
// [1024,1152)); KV output now HALF into h_kv (ld 1024).
// ---------------------------------------------------------------------------
__global__ void __launch_bounds__(256, 2)
mm_qkv(const __half* __restrict__ qln, const __half* __restrict__ zc,
       const __half* __restrict__ wh,
       __half* __restrict__ qh, __half* __restrict__ kvout) {
    extern __shared__ __half smh[];
    const uint32_t base = smem_u32(smh);

    const int tid = threadIdx.x;
    const int lane = tid & 31;
    const int wid = tid >> 5;
    const int wm = (wid >> 2) * 64;
    const int wn = (wid & 3) * 32;

    const bool isQ = blockIdx.x < 1024;
    int bRow, bCol;
    const __half* A;
    const __half* Bt;
    if (isQ) {
        int b = blockIdx.x;
        bCol = (b & 3) * 128;
        bRow = (b >> 2) * 128;
        A = qln;
        Bt = wh + OFF_WQ;
    } else {
        int b = blockIdx.x - 1024;
        bCol = (b & 7) * 128;
        bRow = (b >> 3) * 128;
        A = zc;
        Bt = wh + OFF_WK;     // [Wk|Wv] combined [1024,512]
    }
    const int gid = lane >> 2;
    const int tig = lane & 3;
    const int lr = lane & 7;
    const int aRow = wm + lr + ((lane >> 3) & 1) * 8;
    const int aK   = ((lane >> 4) & 1) * 8;
    const int bRw  = wn + lr + ((lane >> 4) & 1) * 8;
    const int bK   = ((lane >> 3) & 1) * 8;

    float acc[4][4][4];
    #pragma unroll
    for (int mi = 0; mi < 4; mi++)
        #pragma unroll
        for (int ni = 0; ni < 4; ni++)
            #pragma unroll
            for (int r = 0; r < 4; r++) acc[mi][ni][r] = 0.f;

    auto load = [&](int chunk, int s) {
        int k0 = chunk * 64;
        #pragma unroll
        for (int it = 0; it < 4; it++) {
            int idx = tid + it * 256;
            int r = idx >> 3, cs = idx & 7;
            cp_async16(base + (uint32_t)(s * 9216 + r * 72 + cs * 8) * 2,
                       A + (size_t)(bRow + r) * 512 + k0 + cs * 8);
        }
        #pragma unroll
        for (int it = 0; it < 4; it++) {
            int idx = tid + it * 256;
            int r = idx >> 3, cs = idx & 7;
            cp_async16(base + (uint32_t)(18432 + s * 9216 + r * 72 + cs * 8) * 2,
                       Bt + (size_t)(bCol + r) * 512 + k0 + cs * 8);
        }
    };

    load(0, 0); cp_commit();
    load(1, 1); cp_commit();

    #pragma unroll 1
    for (int j = 0; j < 8; j++) {
        int s = j & 1;
        if (j + 1 < 8) cp_wait1(); else cp_wait0();
        __syncthreads();

        uint32_t aBase = base + (uint32_t)(s * 9216 + aRow * 72 + aK) * 2;
        uint32_t bBase = base + (uint32_t)(18432 + s * 9216 + bRw * 72 + bK) * 2;
        #pragma unroll
        for (int ks = 0; ks < 4; ks++) {
            uint32_t af[4][4];
            #pragma unroll
            for (int mi = 0; mi < 4; mi++)
                ldsm4(af[mi][0], af[mi][1], af[mi][2], af[mi][3],
                      aBase + (uint32_t)(mi * 16 * 72 + ks * 16) * 2);
            uint32_t bf[4][2];
            ldsm4(bf[0][0], bf[0][1], bf[1][0], bf[1][1],
                  bBase + (uint32_t)(ks * 16) * 2);
            ldsm4(bf[2][0], bf[2][1], bf[3][0], bf[3][1],
                  bBase + (uint32_t)(16 * 72 + ks * 16) * 2);
            #pragma unroll
            for (int mi = 0; mi < 4; mi++)
                #pragma unroll
                for (int ni = 0; ni < 4; ni++)
                    mma16(acc[mi][ni], af[mi][0], af[mi][1], af[mi][2], af[mi][3],
                          bf[ni][0], bf[ni][1]);
        }
        __syncthreads();
        if (j + 2 < 8) { load(j + 2, s); cp_commit(); }
    }

    #pragma unroll
    for (int mi = 0; mi < 4; mi++) {
        #pragma unroll
        for (int ni = 0; ni < 4; ni++) {
            int r0 = bRow + wm + mi * 16 + gid;
            int c0 = bCol + wn + ni * 8 + tig * 2;
            #pragma unroll
            for (int hi = 0; hi < 2; hi++) {
                int r = r0 + hi * 8;
                float e0 = acc[mi][ni][hi * 2 + 0];
                float e1 = acc[mi][ni][hi * 2 + 1];
                if (isQ) {
                    *(__half2*)(qh + (size_t)r * 512 + c0) =
                        __floats2half2_rn(e0, e1);
                } else {
                    *(__half2*)(kvout + (size_t)r * 1024 + c0) =
                        __floats2half2_rn(e0, e1);
                }
            }
        }
    }
}

// ---------------------------------------------------------------------------
// Per-dim head-mixing attention (all-half operands; q pre-scaled by 0.125)
// K/V from combined half [NCUR, 1024] buffer: cols [0,512)=kc, [512,1024)=vc
// ---------------------------------------------------------------------------
__global__ void attn_kernel(const __half* __restrict__ q,
                            const __half* __restrict__ kv,
                            const __half* __restrict__ e,
                            __half* __restrict__ att) {
    int idx = blockIdx.x * blockDim.x + threadIdx.x;
    int d = idx & 63;
    int row = idx >> 6;          // bta
    int a = row & (AA - 1);
    int bt = row >> 9;
    int b = bt >> 4;
    const __half* qr = q + (size_t)row * ZZ;
    const __half* kr = kv + (size_t)(b * AA + a) * (2 * ZZ);
    const __half* er = e + (size_t)bt * ZZ;
    float qv[8], kvv[8], vv[8];
    #pragma unroll
    for (int h = 0; h < 8; h++) {
        int o = h * 64 + d;
        qv[h] = __half2float(qr[o]);
        kvv[h] = __half2float(kr[o]) + __half2float(er[o]);
        vv[h] = __half2float(kr[ZZ + o]);
    }
    __half* outr = att + (size_t)row * ZZ;
    #pragma unroll
    for (int i = 0; i < 8; i++) {
        float l[8], m = -1e30f;
        #pragma unroll
        for (int j = 0; j < 8; j++) { l[j] = qv[i] * kvv[j]; m = fmaxf(m, l[j]); }
        float s = 0.f, o = 0.f;
        #pragma unroll
        for (int j = 0; j < 8; j++) {
            float p = __expf(l[j] - m);
            s += p;
            o += p * vv[j];
        }
        outr[i * 64 + d] = __float2half(o / s);
    }
}

// ---------------------------------------------------------------------------
// Gate scalar + z_mid LN, 128 threads/row.
// z_pred and o both read as half from cat; writes half z_mid.
// ---------------------------------------------------------------------------
__global__ void gate_zmid_kernel(const float* __restrict__ gdot,
                                 const float* __restrict__ bg2,
                                 const __half* __restrict__ cat,
                                 const float* __restrict__ g_lno,
                                 const float* __restrict__ b_lno,
                                 __half* __restrict__ zmidH) {
    __shared__ float sb[32];
    int row = blockIdx.x;
    int tid = threadIdx.x;
    float dot = gdot[row] + gdot[NROWS + row] + gdot[2 * NROWS + row]
              + gdot[3 * NROWS + row];
    float g = 1.0f / (1.0f + expf(-(dot + bg2[0])));

    const __half* orow = cat + (size_t)row * (2 * ZZ);        // [0,512) = o
    const __half* zr   = orow + ZZ;                           // [512,1024) = z_pred
    float y[4];
    float s = 0.f;
    #pragma unroll
    for (int k = 0; k < 4; k++) {
        int c = tid + k * 128;
        y[k] = __half2float(zr[c]) + g * __half2float(orow[c]);
        s += y[k];
    }
    float mean = blockSum128(s, sb) * (1.0f / ZZ);
    float s2 = 0.f;
    #pragma unroll
    for (int k = 0; k < 4; k++) { float d = y[k] - mean; s2 += d * d; }
    float var = blockSum128(s2, sb) * (1.0f / ZZ);
    float rstd = rsqrtf(var + 1e-5f);
    __half* zmh = zmidH + (size_t)row * ZZ;
    #pragma unroll
    for (int k = 0; k < 4; k++) {
        int c = tid + k * 128;
        float v = (y[k] - mean) * rstd * g_lno[c] + b_lno[c];
        zmh[c] = __float2half(v);
    }
}

// ---------------------------------------------------------------------------
// Launch (8 nodes)
// ---------------------------------------------------------------------------
extern "C" void kernel_launch(void* const* d_in, const int* in_sizes, int n_in,
                              void* d_out, int out_size) {
    const float* z_current = (const float*)d_in[0];
    const float* z_pred    = (const float*)d_in[1];
    const float* actions   = (const float*)d_in[2];
    const float* Wq        = (const float*)d_in[3];
    const float* Wk        = (const float*)d_in[4];
    const float* Wv        = (const float*)d_in[5];
    const float* We        = (const float*)d_in[6];
    const float* Wo        = (const float*)d_in[7];
    const float* g_lnq     = (const float*)d_in[8];
    const float* b_lnq     = (const float*)d_in[9];
    const float* g_lno     = (const float*)d_in[10];
    const float* b_lno     = (const float*)d_in[11];
    const float* W_ff1     = (const float*)d_in[12];
    const float* b_ff1     = (const float*)d_in[13];
    const float* W_ff2     = (const float*)d_in[14];
    const float* b_ff2     = (const float*)d_in[15];
    const float* W_edge    = (const float*)d_in[16];
    const float* b_edge    = (const float*)d_in[17];
    const float* Wg1       = (const float*)d_in[18];
    const float* bg1       = (const float*)d_in[19];
    const float* Wg2       = (const float*)d_in[20];
    const float* bg2       = (const float*)d_in[21];
    float* out = (float*)d_out;

    void *pgd, *pkv, *pe;
    void *pqln, *pq, *patt, *pcat, *phzc, *phzm, *phhid, *phw;
    cudaGetSymbolAddress(&pgd,  d_gdot);
    cudaGetSymbolAddress(&pkv,  h_kv);
    cudaGetSymbolAddress(&pe,   h_e);
    cudaGetSymbolAddress(&pqln, h_qln);
    cudaGetSymbolAddress(&pq,   h_q);
    cudaGetSymbolAddress(&patt, h_att);
    cudaGetSymbolAddress(&pcat, h_cat);
    cudaGetSymbolAddress(&phzc, h_zc);
    cudaGetSymbolAddress(&phzm, h_zmid);
    cudaGetSymbolAddress(&phhid,h_hid);
    cudaGetSymbolAddress(&phw,  h_w);
    float* gdot = (float*)pgd;
    __half* kv  = (__half*)pkv;
    __half* e   = (__half*)pe;
    __half* qln = (__half*)pqln;
    __half* qh  = (__half*)pq;
    __half* att = (__half*)patt;
    __half* cat = (__half*)pcat;
    __half* zc  = (__half*)phzc;
    __half* zmh = (__half*)phzm;
    __half* hid = (__half*)phhid;
    __half* wh  = (__half*)phw;

    cudaFuncSetAttribute(mm_qkv,
                         cudaFuncAttributeMaxDynamicSharedMemorySize, MM_SMEM);
    cudaFuncSetAttribute(mm_h<false,false,false,false,true,false>,
                         cudaFuncAttributeMaxDynamicSharedMemorySize, MM_SMEM);
    cudaFuncSetAttribute(mm_h<true,true,false,false,false,true>,
                         cudaFuncAttributeMaxDynamicSharedMemorySize, MM_SMEM);
    cudaFuncSetAttribute(mm_h<true,true,false,false,true,false>,
                         cudaFuncAttributeMaxDynamicSharedMemorySize, MM_SMEM);
    cudaFuncSetAttribute(mm_h<true,false,true,true,false,false>,
                         cudaFuncAttributeMaxDynamicSharedMemorySize, MM_SMEM);

    // 1) all input-only prep: transposes + halfcopy + LN + edge (half e)
    prep_all<<<ALL_BLKS, 256>>>(Wq, Wk, Wv, Wo, Wg1, W_ff1, W_ff2,
                                z_current, z_pred, g_lnq, b_lnq,
                                actions, W_edge, b_edge, We,
                                wh, zc, qln, cat, e);
    // 2) Q + K/V projections in one launch (KV -> half)
    mm_qkv<<<1152, 256, MM_SMEM>>>(qln, zc, wh, qh, kv);
    // 3) attention -> att (half)
    attn_kernel<<<(NROWS * 64) / 256, 256>>>(qh, kv, e, att);
    // 4) o = att @ Wo -> half into cat[:,0:512]
    mm_h<false,false,false,false,true,false><<<dim3(4, 256), 256, MM_SMEM>>>(
        att, wh + OFF_WO, nullptr, nullptr, nullptr, cat, nullptr, nullptr,
        ZZ, ZZ, ZZ, ZZ, 2*ZZ, 0);
    // 5) gate: gelu(cat @ Wg1 + bg1) . Wg2 -> gdot partials
    mm_h<true,true,false,false,false,true><<<dim3(4, 256), 256, MM_SMEM>>>(
        cat, wh + OFF_WG1, bg1, nullptr, nullptr, nullptr, Wg2, gdot,
        2*ZZ, ZZ, 2*ZZ, 2*ZZ, ZZ, 0);
    // 6) gate scalar + z_mid -> zmh (all-half inputs from cat)
    gate_zmid_kernel<<<NROWS, 128>>>(gdot, bg2, cat, g_lno, b_lno, zmh);
    // 7) hidden = gelu(z_mid @ W_ff1 + b_ff1) -> half
    mm_h<true,true,false,false,true,false><<<dim3(16, 256), 256, MM_SMEM>>>(
        zmh, wh + OFF_FF1, b_ff1, nullptr, nullptr, hid, nullptr, nullptr,
        ZZ, 4*ZZ, ZZ, ZZ, 4*ZZ, 0);
    // 8) out = hidden @ W_ff2 + b_ff2 + half(z_mid) -> f32
    mm_h<true,false,true,true,false,false><<<dim3(4, 256), 256, MM_SMEM>>>(
        hid, wh + OFF_FF2, b_ff2, zmh, out, nullptr, nullptr, nullptr,
        4*ZZ, ZZ, 4*ZZ, 4*ZZ, ZZ, ZZ);
}